// round 7
// baseline (speedup 1.0000x reference)
#include <cuda_runtime.h>

#define N_NODES_C 100000
#define BN_EPS 1e-5f

// Scratch (device globals — no allocation allowed)
__device__ float g_agg[(size_t)N_NODES_C * 128];
__device__ float g_h[(size_t)N_NODES_C * 128];
__device__ float g_deg[N_NODES_C];
__device__ float g_invdeg[N_NODES_C];

// ---------------------------------------------------------------------------
__global__ void zero_kernel(float4* __restrict__ p, int n4) {
    int i = blockIdx.x * blockDim.x + threadIdx.x;
    if (i < n4) p[i] = make_float4(0.f, 0.f, 0.f, 0.f);
}

__global__ void deg_kernel(const int* __restrict__ ei, int E,
                           float* __restrict__ deg) {
    int e = blockIdx.x * blockDim.x + threadIdx.x;
    if (e < E) {
        int dst = ei[(size_t)E + e];
        atomicAdd(&deg[dst], 1.0f);
    }
}

__global__ void invdeg_kernel(const float* __restrict__ deg,
                              float* __restrict__ invdeg, int n) {
    int i = blockIdx.x * blockDim.x + threadIdx.x;
    if (i < n) invdeg[i] = 1.0f / fmaxf(deg[i], 1.0f);
}

// One warp per edge: 32 lanes; each lane loads a float4 of the source row and
// scatters it with 4 scalar atomicAdds (REDG.E.ADD.F32 — result unused).
__global__ void scatter_kernel(const float4* __restrict__ feat,
                               const int* __restrict__ ei, int E,
                               float* __restrict__ agg) {
    long long gid = (long long)blockIdx.x * blockDim.x + threadIdx.x;
    int e = (int)(gid >> 5);
    if (e >= E) return;
    int lane = (int)(gid & 31);
    int src = ei[e];
    int dst = ei[(size_t)E + e];
    float4 v = feat[(size_t)src * 32 + lane];
    float* p = agg + (size_t)dst * 128 + lane * 4;
    atomicAdd(p + 0, v.x);
    atomicAdd(p + 1, v.y);
    atomicAdd(p + 2, v.z);
    atomicAdd(p + 3, v.w);
}

// ---------------------------------------------------------------------------
// Fused SAGE GEMM: out[n, j] = epi( sum_k agg[n,k]*invdeg[n]*Wl[j,k]
//                                 + sum_k x2[n,k]*Wr[j,k] + bias[j] )
// K = 256 (two 128 halves). BM=128 nodes, BN_OUT in {128, 64}.
// 256 threads; micro-tile 8 x TN per thread.
template<int BN_OUT, int TN, bool BN_RELU>
__global__ __launch_bounds__(256)
void sage_gemm_kernel(const float* __restrict__ agg,
                      const float* __restrict__ x2,
                      const float* __restrict__ invdeg,
                      const float* __restrict__ Wl,
                      const float* __restrict__ Wr,
                      const float* __restrict__ bias,
                      const float* __restrict__ gamma,
                      const float* __restrict__ beta,
                      const float* __restrict__ mean,
                      const float* __restrict__ var,
                      float* __restrict__ out, int N) {
    constexpr int BM = 128;
    constexpr int BK = 16;
    constexpr int ASTR = BM + 4;      // 132, pad vs bank conflicts
    constexpr int WSTR = BN_OUT + 4;
    __shared__ float As[BK * ASTR];
    __shared__ float Ws[BK * WSTR];

    const int tid = threadIdx.x;
    const int tm = tid >> 4;   // 0..15 -> row group of 8
    const int tn = tid & 15;   // 0..15 -> col group of TN
    const int blockRow = blockIdx.x * BM;

    float acc[8][TN];
#pragma unroll
    for (int i = 0; i < 8; i++)
#pragma unroll
        for (int j = 0; j < TN; j++) acc[i][j] = 0.f;

    for (int kt = 0; kt < 256 / BK; ++kt) {
        const int kbase = kt * BK;
        const bool firstHalf = (kbase < 128);
        const float* Asrc = firstHalf ? agg : x2;
        const int kloc = firstHalf ? kbase : (kbase - 128);

        // A tile: 128 rows x 16 k = 512 float4, 2 per thread, store k-major
#pragma unroll
        for (int p = 0; p < 2; ++p) {
            int f4id = tid + p * 256;
            int row = f4id >> 2;
            int q = f4id & 3;
            int n = blockRow + row;
            float4 v = make_float4(0.f, 0.f, 0.f, 0.f);
            if (n < N) {
                v = *(const float4*)(Asrc + (size_t)n * 128 + kloc + q * 4);
                if (firstHalf) {
                    float s = invdeg[n];
                    v.x *= s; v.y *= s; v.z *= s; v.w *= s;
                }
            }
            As[(q * 4 + 0) * ASTR + row] = v.x;
            As[(q * 4 + 1) * ASTR + row] = v.y;
            As[(q * 4 + 2) * ASTR + row] = v.z;
            As[(q * 4 + 3) * ASTR + row] = v.w;
        }

        // W tile: BN_OUT rows x 16 k  (W row stride = 128)
        const float* Wsrc = firstHalf ? Wl : Wr;
        constexpr int WLOADS = (BN_OUT * 4) / 256;  // 2 (128) or 1 (64)
#pragma unroll
        for (int p = 0; p < WLOADS; ++p) {
            int f4id = tid + p * 256;
            int j = f4id >> 2;
            int q = f4id & 3;
            float4 v = *(const float4*)(Wsrc + (size_t)j * 128 + kloc + q * 4);
            Ws[(q * 4 + 0) * WSTR + j] = v.x;
            Ws[(q * 4 + 1) * WSTR + j] = v.y;
            Ws[(q * 4 + 2) * WSTR + j] = v.z;
            Ws[(q * 4 + 3) * WSTR + j] = v.w;
        }
        __syncthreads();

#pragma unroll
        for (int kk = 0; kk < BK; ++kk) {
            float a[8], b[TN];
#pragma unroll
            for (int i = 0; i < 8; i += 4)
                *(float4*)&a[i] = *(const float4*)&As[kk * ASTR + tm * 8 + i];
#pragma unroll
            for (int j = 0; j < TN; j += 4)
                *(float4*)&b[j] = *(const float4*)&Ws[kk * WSTR + tn * TN + j];
#pragma unroll
            for (int i = 0; i < 8; i++)
#pragma unroll
                for (int j = 0; j < TN; j++) acc[i][j] += a[i] * b[j];
        }
        __syncthreads();
    }

    // Epilogue: fold bias + (optional) BN scale/shift + ReLU
    float sj[TN], tj[TN];
#pragma unroll
    for (int j = 0; j < TN; j++) {
        int col = tn * TN + j;
        if (BN_RELU) {
            float s = gamma[col] * rsqrtf(var[col] + BN_EPS);
            sj[j] = s;
            tj[j] = beta[col] - mean[col] * s + bias[col] * s;
        } else {
            sj[j] = 1.f;
            tj[j] = bias[col];
        }
    }
#pragma unroll
    for (int i = 0; i < 8; i++) {
        int n = blockRow + tm * 8 + i;
        if (n < N) {
            float vals[TN];
#pragma unroll
            for (int j = 0; j < TN; j++) {
                float c = acc[i][j] * sj[j] + tj[j];
                if (BN_RELU) c = fmaxf(c, 0.f);
                vals[j] = c;
            }
#pragma unroll
            for (int j = 0; j < TN; j += 4)
                *(float4*)(out + (size_t)n * BN_OUT + tn * TN + j) =
                    *(const float4*)&vals[j];
        }
    }
}

// ---------------------------------------------------------------------------
extern "C" void kernel_launch(void* const* d_in, const int* in_sizes, int n_in,
                              void* d_out, int out_size) {
    const float* x        = (const float*)d_in[0];
    const int* ei         = (const int*)d_in[1];   // int32 (JAX x64 disabled)
    const float* W1l      = (const float*)d_in[2];
    const float* b1l      = (const float*)d_in[3];
    const float* W1r      = (const float*)d_in[4];
    const float* bn_gamma = (const float*)d_in[5];
    const float* bn_beta  = (const float*)d_in[6];
    const float* bn_mean  = (const float*)d_in[7];
    const float* bn_var   = (const float*)d_in[8];
    const float* W2l      = (const float*)d_in[9];
    const float* b2l      = (const float*)d_in[10];
    const float* W2r      = (const float*)d_in[11];
    float* out            = (float*)d_out;

    const int N = N_NODES_C;
    const int E = in_sizes[1] / 2;

    float *agg, *h, *deg, *invdeg;
    cudaGetSymbolAddress((void**)&agg, g_agg);
    cudaGetSymbolAddress((void**)&h, g_h);
    cudaGetSymbolAddress((void**)&deg, g_deg);
    cudaGetSymbolAddress((void**)&invdeg, g_invdeg);

    const int aggF4 = N * 128 / 4;   // 3.2M float4
    const int degF4 = N / 4;         // 25k float4

    // degree (shared by both layers)
    zero_kernel<<<(degF4 + 255) / 256, 256>>>((float4*)deg, degF4);
    deg_kernel<<<(E + 255) / 256, 256>>>(ei, E, deg);
    invdeg_kernel<<<(N + 255) / 256, 256>>>(deg, invdeg, N);

    // Layer 1: agg = scatter-sum(x[src] -> dst)
    zero_kernel<<<(aggF4 + 255) / 256, 256>>>((float4*)agg, aggF4);
    {
        long long threads = (long long)E * 32;
        int blocks = (int)((threads + 255) / 256);
        scatter_kernel<<<blocks, 256>>>((const float4*)x, ei, E, agg);
    }
    // h = relu(bn(agg/deg @ W1l^T + b1l + x @ W1r^T))
    sage_gemm_kernel<128, 8, true><<<(N + 127) / 128, 256>>>(
        agg, x, invdeg, W1l, W1r, b1l, bn_gamma, bn_beta, bn_mean, bn_var,
        h, N);

    // Layer 2
    zero_kernel<<<(aggF4 + 255) / 256, 256>>>((float4*)agg, aggF4);
    {
        long long threads = (long long)E * 32;
        int blocks = (int)((threads + 255) / 256);
        scatter_kernel<<<blocks, 256>>>((const float4*)h, ei, E, agg);
    }
    // out = agg/deg @ W2l^T + b2l + h @ W2r^T
    sage_gemm_kernel<64, 4, false><<<(N + 127) / 128, 256>>>(
        agg, h, invdeg, W2l, W2r, b2l, nullptr, nullptr, nullptr, nullptr,
        out, N);
}

// round 8
// speedup vs baseline: 1.7046x; 1.7046x over previous
#include <cuda_runtime.h>

#define N_NODES_C 100000
#define BN_EPS 1e-5f

// Scratch (device globals — no allocation allowed)
__device__ float g_agg[(size_t)N_NODES_C * 128];
__device__ float g_h[(size_t)N_NODES_C * 128];
__device__ float g_deg[N_NODES_C];
__device__ float g_invdeg[N_NODES_C];

// ---------------------------------------------------------------------------
__global__ void zero_kernel(float4* __restrict__ p, int n4) {
    int i = blockIdx.x * blockDim.x + threadIdx.x;
    if (i < n4) p[i] = make_float4(0.f, 0.f, 0.f, 0.f);
}

__global__ void deg_kernel(const int* __restrict__ ei, int E,
                           float* __restrict__ deg) {
    int e = blockIdx.x * blockDim.x + threadIdx.x;
    if (e < E) {
        int dst = ei[(size_t)E + e];
        atomicAdd(&deg[dst], 1.0f);
    }
}

__global__ void invdeg_kernel(const float* __restrict__ deg,
                              float* __restrict__ invdeg, int n) {
    int i = blockIdx.x * blockDim.x + threadIdx.x;
    if (i < n) invdeg[i] = 1.0f / fmaxf(deg[i], 1.0f);
}

// Vectorized global float reduction (PTX 8.1+, sm_90+): one 16B RED per lane.
__device__ __forceinline__ void red_add_v4(float* addr, float4 v) {
    unsigned long long gaddr =
        (unsigned long long)__cvta_generic_to_global((void*)addr);
    asm volatile("red.global.add.v4.f32 [%0], {%1, %2, %3, %4};"
                 :: "l"(gaddr), "f"(v.x), "f"(v.y), "f"(v.z), "f"(v.w)
                 : "memory");
}

// One warp per edge: 32 lanes; each lane loads a float4 of the source row and
// scatters it with a single vector RED (4x fewer atomic instructions than
// scalar atomicAdd; same bytes).
__global__ void scatter_kernel(const float4* __restrict__ feat,
                               const int* __restrict__ ei, int E,
                               float* __restrict__ agg) {
    long long gid = (long long)blockIdx.x * blockDim.x + threadIdx.x;
    int e = (int)(gid >> 5);
    if (e >= E) return;
    int lane = (int)(gid & 31);
    int src = ei[e];
    int dst = ei[(size_t)E + e];
    float4 v = feat[(size_t)src * 32 + lane];
    red_add_v4(agg + (size_t)dst * 128 + lane * 4, v);
}

// ---------------------------------------------------------------------------
// Fused SAGE GEMM: out[n, j] = epi( sum_k agg[n,k]*invdeg[n]*Wl[j,k]
//                                 + sum_k x2[n,k]*Wr[j,k] + bias[j] )
// K = 256 (two 128 halves). BM=128 nodes, BN_OUT in {128, 64}.
// 256 threads; micro-tile 8 x TN per thread.
template<int BN_OUT, int TN, bool BN_RELU>
__global__ __launch_bounds__(256)
void sage_gemm_kernel(const float* __restrict__ agg,
                      const float* __restrict__ x2,
                      const float* __restrict__ invdeg,
                      const float* __restrict__ Wl,
                      const float* __restrict__ Wr,
                      const float* __restrict__ bias,
                      const float* __restrict__ gamma,
                      const float* __restrict__ beta,
                      const float* __restrict__ mean,
                      const float* __restrict__ var,
                      float* __restrict__ out, int N) {
    constexpr int BM = 128;
    constexpr int BK = 16;
    constexpr int ASTR = BM + 4;      // 132, pad vs bank conflicts
    constexpr int WSTR = BN_OUT + 4;
    __shared__ float As[BK * ASTR];
    __shared__ float Ws[BK * WSTR];

    const int tid = threadIdx.x;
    const int tm = tid >> 4;   // 0..15 -> row group of 8
    const int tn = tid & 15;   // 0..15 -> col group of TN
    const int blockRow = blockIdx.x * BM;

    float acc[8][TN];
#pragma unroll
    for (int i = 0; i < 8; i++)
#pragma unroll
        for (int j = 0; j < TN; j++) acc[i][j] = 0.f;

    for (int kt = 0; kt < 256 / BK; ++kt) {
        const int kbase = kt * BK;
        const bool firstHalf = (kbase < 128);
        const float* Asrc = firstHalf ? agg : x2;
        const int kloc = firstHalf ? kbase : (kbase - 128);

        // A tile: 128 rows x 16 k = 512 float4, 2 per thread, store k-major
#pragma unroll
        for (int p = 0; p < 2; ++p) {
            int f4id = tid + p * 256;
            int row = f4id >> 2;
            int q = f4id & 3;
            int n = blockRow + row;
            float4 v = make_float4(0.f, 0.f, 0.f, 0.f);
            if (n < N) {
                v = *(const float4*)(Asrc + (size_t)n * 128 + kloc + q * 4);
                if (firstHalf) {
                    float s = invdeg[n];
                    v.x *= s; v.y *= s; v.z *= s; v.w *= s;
                }
            }
            As[(q * 4 + 0) * ASTR + row] = v.x;
            As[(q * 4 + 1) * ASTR + row] = v.y;
            As[(q * 4 + 2) * ASTR + row] = v.z;
            As[(q * 4 + 3) * ASTR + row] = v.w;
        }

        // W tile: BN_OUT rows x 16 k  (W row stride = 128)
        const float* Wsrc = firstHalf ? Wl : Wr;
        constexpr int WLOADS = (BN_OUT * 4) / 256;  // 2 (128) or 1 (64)
#pragma unroll
        for (int p = 0; p < WLOADS; ++p) {
            int f4id = tid + p * 256;
            int j = f4id >> 2;
            int q = f4id & 3;
            float4 v = *(const float4*)(Wsrc + (size_t)j * 128 + kloc + q * 4);
            Ws[(q * 4 + 0) * WSTR + j] = v.x;
            Ws[(q * 4 + 1) * WSTR + j] = v.y;
            Ws[(q * 4 + 2) * WSTR + j] = v.z;
            Ws[(q * 4 + 3) * WSTR + j] = v.w;
        }
        __syncthreads();

#pragma unroll
        for (int kk = 0; kk < BK; ++kk) {
            float a[8], b[TN];
#pragma unroll
            for (int i = 0; i < 8; i += 4)
                *(float4*)&a[i] = *(const float4*)&As[kk * ASTR + tm * 8 + i];
#pragma unroll
            for (int j = 0; j < TN; j += 4)
                *(float4*)&b[j] = *(const float4*)&Ws[kk * WSTR + tn * TN + j];
#pragma unroll
            for (int i = 0; i < 8; i++)
#pragma unroll
                for (int j = 0; j < TN; j++) acc[i][j] += a[i] * b[j];
        }
        __syncthreads();
    }

    // Epilogue: fold bias + (optional) BN scale/shift + ReLU
    float sj[TN], tj[TN];
#pragma unroll
    for (int j = 0; j < TN; j++) {
        int col = tn * TN + j;
        if (BN_RELU) {
            float s = gamma[col] * rsqrtf(var[col] + BN_EPS);
            sj[j] = s;
            tj[j] = beta[col] - mean[col] * s + bias[col] * s;
        } else {
            sj[j] = 1.f;
            tj[j] = bias[col];
        }
    }
#pragma unroll
    for (int i = 0; i < 8; i++) {
        int n = blockRow + tm * 8 + i;
        if (n < N) {
            float vals[TN];
#pragma unroll
            for (int j = 0; j < TN; j++) {
                float c = acc[i][j] * sj[j] + tj[j];
                if (BN_RELU) c = fmaxf(c, 0.f);
                vals[j] = c;
            }
#pragma unroll
            for (int j = 0; j < TN; j += 4)
                *(float4*)(out + (size_t)n * BN_OUT + tn * TN + j) =
                    *(const float4*)&vals[j];
        }
    }
}

// ---------------------------------------------------------------------------
extern "C" void kernel_launch(void* const* d_in, const int* in_sizes, int n_in,
                              void* d_out, int out_size) {
    const float* x        = (const float*)d_in[0];
    const int* ei         = (const int*)d_in[1];   // int32 (JAX x64 disabled)
    const float* W1l      = (const float*)d_in[2];
    const float* b1l      = (const float*)d_in[3];
    const float* W1r      = (const float*)d_in[4];
    const float* bn_gamma = (const float*)d_in[5];
    const float* bn_beta  = (const float*)d_in[6];
    const float* bn_mean  = (const float*)d_in[7];
    const float* bn_var   = (const float*)d_in[8];
    const float* W2l      = (const float*)d_in[9];
    const float* b2l      = (const float*)d_in[10];
    const float* W2r      = (const float*)d_in[11];
    float* out            = (float*)d_out;

    const int N = N_NODES_C;
    const int E = in_sizes[1] / 2;

    float *agg, *h, *deg, *invdeg;
    cudaGetSymbolAddress((void**)&agg, g_agg);
    cudaGetSymbolAddress((void**)&h, g_h);
    cudaGetSymbolAddress((void**)&deg, g_deg);
    cudaGetSymbolAddress((void**)&invdeg, g_invdeg);

    const int aggF4 = N * 128 / 4;   // 3.2M float4
    const int degF4 = N / 4;         // 25k float4

    // degree (shared by both layers)
    zero_kernel<<<(degF4 + 255) / 256, 256>>>((float4*)deg, degF4);
    deg_kernel<<<(E + 255) / 256, 256>>>(ei, E, deg);
    invdeg_kernel<<<(N + 255) / 256, 256>>>(deg, invdeg, N);

    // Layer 1: agg = scatter-sum(x[src] -> dst)
    zero_kernel<<<(aggF4 + 255) / 256, 256>>>((float4*)agg, aggF4);
    {
        long long threads = (long long)E * 32;
        int blocks = (int)((threads + 255) / 256);
        scatter_kernel<<<blocks, 256>>>((const float4*)x, ei, E, agg);
    }
    // h = relu(bn(agg/deg @ W1l^T + b1l + x @ W1r^T))
    sage_gemm_kernel<128, 8, true><<<(N + 127) / 128, 256>>>(
        agg, x, invdeg, W1l, W1r, b1l, bn_gamma, bn_beta, bn_mean, bn_var,
        h, N);

    // Layer 2
    zero_kernel<<<(aggF4 + 255) / 256, 256>>>((float4*)agg, aggF4);
    {
        long long threads = (long long)E * 32;
        int blocks = (int)((threads + 255) / 256);
        scatter_kernel<<<blocks, 256>>>((const float4*)h, ei, E, agg);
    }
    // out = agg/deg @ W2l^T + b2l + h @ W2r^T
    sage_gemm_kernel<64, 4, false><<<(N + 127) / 128, 256>>>(
        agg, h, invdeg, W2l, W2r, b2l, nullptr, nullptr, nullptr, nullptr,
        out, N);
}

// round 9
// speedup vs baseline: 2.9344x; 1.7215x over previous
#include <cuda_runtime.h>

#define N_NODES_C 100000
#define E_MAX_C   1600000
#define BN_EPS 1e-5f

// Scratch (device globals — no allocation allowed)
__device__ float g_agg[(size_t)N_NODES_C * 128];
__device__ float g_h[(size_t)N_NODES_C * 128];
__device__ float g_p[(size_t)N_NODES_C * 64];
__device__ int   g_deg[N_NODES_C];
__device__ int   g_rowstart[N_NODES_C];
__device__ int   g_cursor[N_NODES_C];
__device__ int   g_blocksum[128];
__device__ int   g_blockoff[128];
__device__ int   g_edge_src[E_MAX_C];

// ---------------------------------------------------------------------------
// CSR construction
__global__ void hist_kernel(const int* __restrict__ ei, int E,
                            int* __restrict__ deg) {
    int e = blockIdx.x * blockDim.x + threadIdx.x;
    if (e < E) atomicAdd(&deg[ei[(size_t)E + e]], 1);
}

// Per-block inclusive scan (1024 elems/block); writes local-exclusive + block sum.
__global__ void scan1_kernel(const int* __restrict__ deg,
                             int* __restrict__ rowstart,
                             int* __restrict__ blocksum, int n) {
    __shared__ int s[1024];
    int tid = threadIdx.x;
    int i = blockIdx.x * 1024 + tid;
    int v = (i < n) ? deg[i] : 0;
    s[tid] = v;
    __syncthreads();
#pragma unroll
    for (int off = 1; off < 1024; off <<= 1) {
        int t = (tid >= off) ? s[tid - off] : 0;
        __syncthreads();
        s[tid] += t;
        __syncthreads();
    }
    if (i < n) rowstart[i] = s[tid] - v;          // local exclusive
    if (tid == 1023) blocksum[blockIdx.x] = s[tid];
}

__global__ void scan2_kernel(const int* __restrict__ blocksum,
                             int* __restrict__ blockoff, int nb) {
    __shared__ int s[128];
    int tid = threadIdx.x;
    int v = (tid < nb) ? blocksum[tid] : 0;
    s[tid] = v;
    __syncthreads();
#pragma unroll
    for (int off = 1; off < 128; off <<= 1) {
        int t = (tid >= off) ? s[tid - off] : 0;
        __syncthreads();
        s[tid] += t;
        __syncthreads();
    }
    if (tid < nb) blockoff[tid] = s[tid] - v;     // exclusive
}

__global__ void scan3_kernel(int* __restrict__ rowstart,
                             int* __restrict__ cursor,
                             const int* __restrict__ blockoff, int n) {
    int i = blockIdx.x * 1024 + threadIdx.x;
    if (i < n) {
        int r = rowstart[i] + blockoff[blockIdx.x];
        rowstart[i] = r;
        cursor[i] = r;
    }
}

__global__ void fill_kernel(const int* __restrict__ ei, int E,
                            int* __restrict__ cursor,
                            int* __restrict__ edge_src) {
    int e = blockIdx.x * blockDim.x + threadIdx.x;
    if (e < E) {
        int src = ei[e];
        int dst = ei[(size_t)E + e];
        int pos = atomicAdd(&cursor[dst], 1);
        edge_src[pos] = src;
    }
}

// ---------------------------------------------------------------------------
// Gather-aggregate: F4 threads per node (each lane owns one float4 of the row).
// dstv = (sum_{edges} feat[src]) / max(deg,1); if ADD, accumulate into dstbuf.
template<int F4, bool ADD>
__global__ void gather_kernel(const float4* __restrict__ feat,
                              const int* __restrict__ rowstart,
                              const int* __restrict__ deg,
                              const int* __restrict__ edge_src,
                              float4* __restrict__ dstbuf, int N) {
    long long gid = (long long)blockIdx.x * blockDim.x + threadIdx.x;
    int n = (int)(gid / F4);
    if (n >= N) return;
    int lane = (int)(gid % F4);
    int d = deg[n];
    int start = rowstart[n];
    float4 acc = make_float4(0.f, 0.f, 0.f, 0.f);
    int j = 0;
    for (; j + 1 < d; j += 2) {
        int s0 = edge_src[start + j];
        int s1 = edge_src[start + j + 1];
        float4 a = feat[(size_t)s0 * F4 + lane];
        float4 b = feat[(size_t)s1 * F4 + lane];
        acc.x += a.x + b.x; acc.y += a.y + b.y;
        acc.z += a.z + b.z; acc.w += a.w + b.w;
    }
    if (j < d) {
        float4 a = feat[(size_t)edge_src[start + j] * F4 + lane];
        acc.x += a.x; acc.y += a.y; acc.z += a.z; acc.w += a.w;
    }
    float inv = 1.0f / (float)max(d, 1);
    acc.x *= inv; acc.y *= inv; acc.z *= inv; acc.w *= inv;
    float4* p = &dstbuf[(size_t)n * F4 + lane];
    if (ADD) {
        float4 o = *p;
        o.x += acc.x; o.y += acc.y; o.z += acc.z; o.w += acc.w;
        *p = o;
    } else {
        *p = acc;
    }
}

// ---------------------------------------------------------------------------
// GEMM1: h[n,j] = relu(bn( sum_k agg[n,k]*W1l[j,k] + sum_k x[n,k]*W1r[j,k] + b[j] ))
// agg is pre-scaled by invdeg. K=256 (agg half then x half). BN_OUT=128.
__global__ __launch_bounds__(256)
void gemm1_kernel(const float* __restrict__ agg,
                  const float* __restrict__ x2,
                  const float* __restrict__ Wl,
                  const float* __restrict__ Wr,
                  const float* __restrict__ bias,
                  const float* __restrict__ gamma,
                  const float* __restrict__ beta,
                  const float* __restrict__ mean,
                  const float* __restrict__ var,
                  float* __restrict__ out, int N) {
    constexpr int BM = 128, BK = 16, BN_OUT = 128, TN = 8;
    constexpr int ASTR = BM + 4, WSTR = BN_OUT + 4;
    __shared__ float As[BK * ASTR];
    __shared__ float Ws[BK * WSTR];

    const int tid = threadIdx.x;
    const int tm = tid >> 4, tn = tid & 15;
    const int blockRow = blockIdx.x * BM;

    float acc[8][TN];
#pragma unroll
    for (int i = 0; i < 8; i++)
#pragma unroll
        for (int j = 0; j < TN; j++) acc[i][j] = 0.f;

    for (int kt = 0; kt < 16; ++kt) {
        const int kbase = kt * BK;
        const bool firstHalf = (kbase < 128);
        const float* Asrc = firstHalf ? agg : x2;
        const int kloc = firstHalf ? kbase : (kbase - 128);

#pragma unroll
        for (int p = 0; p < 2; ++p) {
            int f4id = tid + p * 256;
            int row = f4id >> 2, q = f4id & 3;
            int n = blockRow + row;
            float4 v = make_float4(0.f, 0.f, 0.f, 0.f);
            if (n < N) v = *(const float4*)(Asrc + (size_t)n * 128 + kloc + q * 4);
            As[(q * 4 + 0) * ASTR + row] = v.x;
            As[(q * 4 + 1) * ASTR + row] = v.y;
            As[(q * 4 + 2) * ASTR + row] = v.z;
            As[(q * 4 + 3) * ASTR + row] = v.w;
        }
        const float* Wsrc = firstHalf ? Wl : Wr;
#pragma unroll
        for (int p = 0; p < 2; ++p) {
            int f4id = tid + p * 256;
            int j = f4id >> 2, q = f4id & 3;
            float4 v = *(const float4*)(Wsrc + (size_t)j * 128 + kloc + q * 4);
            Ws[(q * 4 + 0) * WSTR + j] = v.x;
            Ws[(q * 4 + 1) * WSTR + j] = v.y;
            Ws[(q * 4 + 2) * WSTR + j] = v.z;
            Ws[(q * 4 + 3) * WSTR + j] = v.w;
        }
        __syncthreads();

#pragma unroll
        for (int kk = 0; kk < BK; ++kk) {
            float a[8], b[TN];
#pragma unroll
            for (int i = 0; i < 8; i += 4)
                *(float4*)&a[i] = *(const float4*)&As[kk * ASTR + tm * 8 + i];
#pragma unroll
            for (int j = 0; j < TN; j += 4)
                *(float4*)&b[j] = *(const float4*)&Ws[kk * WSTR + tn * TN + j];
#pragma unroll
            for (int i = 0; i < 8; i++)
#pragma unroll
                for (int j = 0; j < TN; j++) acc[i][j] += a[i] * b[j];
        }
        __syncthreads();
    }

    float sj[TN], tj[TN];
#pragma unroll
    for (int j = 0; j < TN; j++) {
        int col = tn * TN + j;
        float s = gamma[col] * rsqrtf(var[col] + BN_EPS);
        sj[j] = s;
        tj[j] = beta[col] - mean[col] * s + bias[col] * s;
    }
#pragma unroll
    for (int i = 0; i < 8; i++) {
        int n = blockRow + tm * 8 + i;
        if (n < N) {
            float vals[TN];
#pragma unroll
            for (int j = 0; j < TN; j++)
                vals[j] = fmaxf(acc[i][j] * sj[j] + tj[j], 0.f);
#pragma unroll
            for (int j = 0; j < TN; j += 4)
                *(float4*)(out + (size_t)n * 128 + tn * TN + j) =
                    *(const float4*)&vals[j];
        }
    }
}

// ---------------------------------------------------------------------------
// GEMM2: from h (K=128) produce two 64-wide outputs in one pass:
//   cols 0..63   -> p[n]   = h @ W2l^T          (no bias; aggregated later)
//   cols 64..127 -> out[n] = h @ W2r^T + b2l
__global__ __launch_bounds__(256)
void gemm2_kernel(const float* __restrict__ h,
                  const float* __restrict__ W2l,
                  const float* __restrict__ W2r,
                  const float* __restrict__ b2l,
                  float* __restrict__ p_out,
                  float* __restrict__ out, int N) {
    constexpr int BM = 128, BK = 16, TN = 8;
    constexpr int ASTR = BM + 4, WSTR = 128 + 4;
    __shared__ float As[BK * ASTR];
    __shared__ float Ws[BK * WSTR];

    const int tid = threadIdx.x;
    const int tm = tid >> 4, tn = tid & 15;
    const int blockRow = blockIdx.x * BM;

    float acc[8][TN];
#pragma unroll
    for (int i = 0; i < 8; i++)
#pragma unroll
        for (int j = 0; j < TN; j++) acc[i][j] = 0.f;

    for (int kt = 0; kt < 8; ++kt) {
        const int kloc = kt * BK;
#pragma unroll
        for (int p = 0; p < 2; ++p) {
            int f4id = tid + p * 256;
            int row = f4id >> 2, q = f4id & 3;
            int n = blockRow + row;
            float4 v = make_float4(0.f, 0.f, 0.f, 0.f);
            if (n < N) v = *(const float4*)(h + (size_t)n * 128 + kloc + q * 4);
            As[(q * 4 + 0) * ASTR + row] = v.x;
            As[(q * 4 + 1) * ASTR + row] = v.y;
            As[(q * 4 + 2) * ASTR + row] = v.z;
            As[(q * 4 + 3) * ASTR + row] = v.w;
        }
        // B rows: j<64 -> W2l[j], j>=64 -> W2r[j-64]
#pragma unroll
        for (int p = 0; p < 2; ++p) {
            int f4id = tid + p * 256;
            int j = f4id >> 2, q = f4id & 3;
            const float* Wsrc = (j < 64) ? (W2l + (size_t)j * 128)
                                         : (W2r + (size_t)(j - 64) * 128);
            float4 v = *(const float4*)(Wsrc + kloc + q * 4);
            Ws[(q * 4 + 0) * WSTR + j] = v.x;
            Ws[(q * 4 + 1) * WSTR + j] = v.y;
            Ws[(q * 4 + 2) * WSTR + j] = v.z;
            Ws[(q * 4 + 3) * WSTR + j] = v.w;
        }
        __syncthreads();

#pragma unroll
        for (int kk = 0; kk < BK; ++kk) {
            float a[8], b[TN];
#pragma unroll
            for (int i = 0; i < 8; i += 4)
                *(float4*)&a[i] = *(const float4*)&As[kk * ASTR + tm * 8 + i];
#pragma unroll
            for (int j = 0; j < TN; j += 4)
                *(float4*)&b[j] = *(const float4*)&Ws[kk * WSTR + tn * TN + j];
#pragma unroll
            for (int i = 0; i < 8; i++)
#pragma unroll
                for (int j = 0; j < TN; j++) acc[i][j] += a[i] * b[j];
        }
        __syncthreads();
    }

    const bool isP = (tn < 8);           // cols 0..63
    const int colBase = tn * TN;         // global col
#pragma unroll
    for (int i = 0; i < 8; i++) {
        int n = blockRow + tm * 8 + i;
        if (n < N) {
            float vals[TN];
            if (isP) {
#pragma unroll
                for (int j = 0; j < TN; j++) vals[j] = acc[i][j];
#pragma unroll
                for (int j = 0; j < TN; j += 4)
                    *(float4*)(p_out + (size_t)n * 64 + colBase + j) =
                        *(const float4*)&vals[j];
            } else {
#pragma unroll
                for (int j = 0; j < TN; j++)
                    vals[j] = acc[i][j] + b2l[colBase - 64 + j];
#pragma unroll
                for (int j = 0; j < TN; j += 4)
                    *(float4*)(out + (size_t)n * 64 + colBase - 64 + j) =
                        *(const float4*)&vals[j];
            }
        }
    }
}

// ---------------------------------------------------------------------------
extern "C" void kernel_launch(void* const* d_in, const int* in_sizes, int n_in,
                              void* d_out, int out_size) {
    const float* x        = (const float*)d_in[0];
    const int* ei         = (const int*)d_in[1];   // int32 (JAX x64 disabled)
    const float* W1l      = (const float*)d_in[2];
    const float* b1l      = (const float*)d_in[3];
    const float* W1r      = (const float*)d_in[4];
    const float* bn_gamma = (const float*)d_in[5];
    const float* bn_beta  = (const float*)d_in[6];
    const float* bn_mean  = (const float*)d_in[7];
    const float* bn_var   = (const float*)d_in[8];
    const float* W2l      = (const float*)d_in[9];
    const float* b2l      = (const float*)d_in[10];
    const float* W2r      = (const float*)d_in[11];
    float* out            = (float*)d_out;

    const int N = N_NODES_C;
    const int E = in_sizes[1] / 2;

    float *agg, *h, *p;
    int *deg, *rowstart, *cursor, *blocksum, *blockoff, *edge_src;
    cudaGetSymbolAddress((void**)&agg, g_agg);
    cudaGetSymbolAddress((void**)&h, g_h);
    cudaGetSymbolAddress((void**)&p, g_p);
    cudaGetSymbolAddress((void**)&deg, g_deg);
    cudaGetSymbolAddress((void**)&rowstart, g_rowstart);
    cudaGetSymbolAddress((void**)&cursor, g_cursor);
    cudaGetSymbolAddress((void**)&blocksum, g_blocksum);
    cudaGetSymbolAddress((void**)&blockoff, g_blockoff);
    cudaGetSymbolAddress((void**)&edge_src, g_edge_src);

    const int nb = (N + 1023) / 1024;   // 98 scan blocks

    // ---- CSR build (shared by both layers) ----
    cudaMemsetAsync(deg, 0, N * sizeof(int));
    hist_kernel<<<(E + 255) / 256, 256>>>(ei, E, deg);
    scan1_kernel<<<nb, 1024>>>(deg, rowstart, blocksum, N);
    scan2_kernel<<<1, 128>>>(blocksum, blockoff, nb);
    scan3_kernel<<<nb, 1024>>>(rowstart, cursor, blockoff, N);
    fill_kernel<<<(E + 255) / 256, 256>>>(ei, E, cursor, edge_src);

    // ---- Layer 1: agg = mean-gather(x); h = relu(bn(agg@W1l^T + x@W1r^T + b1l))
    {
        long long threads = (long long)N * 32;
        gather_kernel<32, false><<<(int)((threads + 255) / 256), 256>>>(
            (const float4*)x, rowstart, deg, edge_src, (float4*)agg, N);
    }
    gemm1_kernel<<<(N + 127) / 128, 256>>>(
        agg, x, W1l, W1r, b1l, bn_gamma, bn_beta, bn_mean, bn_var, h, N);

    // ---- Layer 2: p = h@W2l^T ; out = h@W2r^T + b2l ; out += mean-gather(p)
    gemm2_kernel<<<(N + 127) / 128, 256>>>(h, W2l, W2r, b2l, p, out, N);
    {
        long long threads = (long long)N * 16;
        gather_kernel<16, true><<<(int)((threads + 255) / 256), 256>>>(
            (const float4*)p, rowstart, deg, edge_src, (float4*)out, N);
    }
}

// round 10
// speedup vs baseline: 4.5955x; 1.5661x over previous
#include <cuda_runtime.h>

#define N_NODES_C 100000
#define E_MAX_C   1600000
#define BN_EPS 1e-5f

// Scratch (device globals — no allocation allowed)
__device__ float g_agg[(size_t)N_NODES_C * 128];
__device__ float g_h[(size_t)N_NODES_C * 128];
__device__ float g_p[(size_t)N_NODES_C * 64];
__device__ int   g_deg[N_NODES_C];
__device__ int   g_rowstart[N_NODES_C];
__device__ int   g_cursor[N_NODES_C];
__device__ int   g_blocksum[128];
__device__ int   g_blockoff[128];
__device__ int   g_edge_src[E_MAX_C];

// ---------------------------------------------------------------------------
// CSR construction
__global__ void hist_kernel(const int* __restrict__ ei, int E,
                            int* __restrict__ deg) {
    int e = blockIdx.x * blockDim.x + threadIdx.x;
    if (e < E) atomicAdd(&deg[ei[(size_t)E + e]], 1);
}

__global__ void scan1_kernel(const int* __restrict__ deg,
                             int* __restrict__ rowstart,
                             int* __restrict__ blocksum, int n) {
    __shared__ int s[1024];
    int tid = threadIdx.x;
    int i = blockIdx.x * 1024 + tid;
    int v = (i < n) ? deg[i] : 0;
    s[tid] = v;
    __syncthreads();
#pragma unroll
    for (int off = 1; off < 1024; off <<= 1) {
        int t = (tid >= off) ? s[tid - off] : 0;
        __syncthreads();
        s[tid] += t;
        __syncthreads();
    }
    if (i < n) rowstart[i] = s[tid] - v;          // local exclusive
    if (tid == 1023) blocksum[blockIdx.x] = s[tid];
}

__global__ void scan2_kernel(const int* __restrict__ blocksum,
                             int* __restrict__ blockoff, int nb) {
    __shared__ int s[128];
    int tid = threadIdx.x;
    int v = (tid < nb) ? blocksum[tid] : 0;
    s[tid] = v;
    __syncthreads();
#pragma unroll
    for (int off = 1; off < 128; off <<= 1) {
        int t = (tid >= off) ? s[tid - off] : 0;
        __syncthreads();
        s[tid] += t;
        __syncthreads();
    }
    if (tid < nb) blockoff[tid] = s[tid] - v;     // exclusive
}

__global__ void scan3_kernel(int* __restrict__ rowstart,
                             int* __restrict__ cursor,
                             const int* __restrict__ blockoff, int n) {
    int i = blockIdx.x * 1024 + threadIdx.x;
    if (i < n) {
        int r = rowstart[i] + blockoff[blockIdx.x];
        rowstart[i] = r;
        cursor[i] = r;
    }
}

__global__ void fill_kernel(const int* __restrict__ ei, int E,
                            int* __restrict__ cursor,
                            int* __restrict__ edge_src) {
    int e = blockIdx.x * blockDim.x + threadIdx.x;
    if (e < E) {
        int src = ei[e];
        int dst = ei[(size_t)E + e];
        int pos = atomicAdd(&cursor[dst], 1);
        edge_src[pos] = src;
    }
}

// ---------------------------------------------------------------------------
// Gather-aggregate: F4 threads per node (each lane owns one float4 of the row).
template<int F4, bool ADD>
__global__ void gather_kernel(const float4* __restrict__ feat,
                              const int* __restrict__ rowstart,
                              const int* __restrict__ deg,
                              const int* __restrict__ edge_src,
                              float4* __restrict__ dstbuf, int N) {
    long long gid = (long long)blockIdx.x * blockDim.x + threadIdx.x;
    int n = (int)(gid / F4);
    if (n >= N) return;
    int lane = (int)(gid % F4);
    int d = deg[n];
    int start = rowstart[n];
    float4 acc = make_float4(0.f, 0.f, 0.f, 0.f);
    int j = 0;
    for (; j + 1 < d; j += 2) {
        int s0 = edge_src[start + j];
        int s1 = edge_src[start + j + 1];
        float4 a = feat[(size_t)s0 * F4 + lane];
        float4 b = feat[(size_t)s1 * F4 + lane];
        acc.x += a.x + b.x; acc.y += a.y + b.y;
        acc.z += a.z + b.z; acc.w += a.w + b.w;
    }
    if (j < d) {
        float4 a = feat[(size_t)edge_src[start + j] * F4 + lane];
        acc.x += a.x; acc.y += a.y; acc.z += a.z; acc.w += a.w;
    }
    float inv = 1.0f / (float)max(d, 1);
    acc.x *= inv; acc.y *= inv; acc.z *= inv; acc.w *= inv;
    float4* p = &dstbuf[(size_t)n * F4 + lane];
    if (ADD) {
        float4 o = *p;
        o.x += acc.x; o.y += acc.y; o.z += acc.z; o.w += acc.w;
        *p = o;
    } else {
        *p = acc;
    }
}

// ---------------------------------------------------------------------------
// TF32 tensor-core GEMM machinery
__device__ __forceinline__ float f2tf32(float f) {
    unsigned u;
    asm("cvt.rna.tf32.f32 %0, %1;" : "=r"(u) : "f"(f));
    return __uint_as_float(u);
}
__device__ __forceinline__ float4 cvt4(float4 v) {
    return make_float4(f2tf32(v.x), f2tf32(v.y), f2tf32(v.z), f2tf32(v.w));
}
__device__ __forceinline__ void mma16n8k8(float* c, const unsigned* a,
                                          const unsigned* b) {
    asm volatile(
        "mma.sync.aligned.m16n8k8.row.col.f32.tf32.tf32.f32 "
        "{%0,%1,%2,%3}, {%4,%5,%6,%7}, {%8,%9}, {%0,%1,%2,%3};"
        : "+f"(c[0]), "+f"(c[1]), "+f"(c[2]), "+f"(c[3])
        : "r"(a[0]), "r"(a[1]), "r"(a[2]), "r"(a[3]), "r"(b[0]), "r"(b[1]));
}

// Block tile 128x128, 8 warps (4M x 2N), warp tile 32x64, BK=32.
// Smem stride 36 floats -> fragment LDS bank = (4g+t) mod 32, conflict-free.
#define GSTR 36

// GEMM1: h = relu(bn( [agg | x] @ [W1l;W1r]^T + b1l )), K=256
__global__ __launch_bounds__(256)
void gemm1_tf32(const float* __restrict__ agg,
                const float* __restrict__ x2,
                const float* __restrict__ Wl,
                const float* __restrict__ Wr,
                const float* __restrict__ bias,
                const float* __restrict__ gamma,
                const float* __restrict__ beta,
                const float* __restrict__ mean,
                const float* __restrict__ var,
                float* __restrict__ out, int N) {
    __shared__ float As[128 * GSTR];
    __shared__ float Ws[128 * GSTR];
    const int tid = threadIdx.x;
    const int lane = tid & 31, warp = tid >> 5;
    const int wm = warp & 3, wn = warp >> 2;
    const int g = lane >> 2, t = lane & 3;
    const int blockRow = blockIdx.x * 128;

    float c[2][8][4];
#pragma unroll
    for (int m = 0; m < 2; m++)
#pragma unroll
        for (int nt = 0; nt < 8; nt++)
#pragma unroll
            for (int q = 0; q < 4; q++) c[m][nt][q] = 0.f;

    for (int kt = 0; kt < 8; ++kt) {
        const float* Asrc = (kt < 4) ? agg : x2;
        const float* Wsrc = (kt < 4) ? Wl : Wr;
        const int kloc = (kt & 3) * 32;
#pragma unroll
        for (int p = 0; p < 4; ++p) {
            int idx = tid + p * 256;
            int row = idx >> 3, kq = (idx & 7) * 4;
            int n = blockRow + row;
            float4 v = make_float4(0.f, 0.f, 0.f, 0.f);
            if (n < N) v = *(const float4*)(Asrc + (size_t)n * 128 + kloc + kq);
            *(float4*)&As[row * GSTR + kq] = cvt4(v);
        }
#pragma unroll
        for (int p = 0; p < 4; ++p) {
            int idx = tid + p * 256;
            int j = idx >> 3, kq = (idx & 7) * 4;
            float4 v = *(const float4*)(Wsrc + (size_t)j * 128 + kloc + kq);
            *(float4*)&Ws[j * GSTR + kq] = cvt4(v);
        }
        __syncthreads();

#pragma unroll
        for (int kc = 0; kc < 4; ++kc) {
            unsigned afr[2][4];
#pragma unroll
            for (int m = 0; m < 2; m++) {
                int r0 = wm * 32 + m * 16 + g;
                afr[m][0] = __float_as_uint(As[r0 * GSTR + kc * 8 + t]);
                afr[m][1] = __float_as_uint(As[(r0 + 8) * GSTR + kc * 8 + t]);
                afr[m][2] = __float_as_uint(As[r0 * GSTR + kc * 8 + t + 4]);
                afr[m][3] = __float_as_uint(As[(r0 + 8) * GSTR + kc * 8 + t + 4]);
            }
#pragma unroll
            for (int nt = 0; nt < 8; nt++) {
                int nrow = wn * 64 + nt * 8 + g;
                unsigned bfr[2] = {
                    __float_as_uint(Ws[nrow * GSTR + kc * 8 + t]),
                    __float_as_uint(Ws[nrow * GSTR + kc * 8 + t + 4])};
                mma16n8k8(c[0][nt], afr[0], bfr);
                mma16n8k8(c[1][nt], afr[1], bfr);
            }
        }
        __syncthreads();
    }

#pragma unroll
    for (int nt = 0; nt < 8; nt++) {
        int col0 = wn * 64 + nt * 8 + 2 * t;
        float s0 = gamma[col0] * rsqrtf(var[col0] + BN_EPS);
        float s1 = gamma[col0 + 1] * rsqrtf(var[col0 + 1] + BN_EPS);
        float t0 = beta[col0] - mean[col0] * s0 + bias[col0] * s0;
        float t1 = beta[col0 + 1] - mean[col0 + 1] * s1 + bias[col0 + 1] * s1;
#pragma unroll
        for (int m = 0; m < 2; m++) {
            int r = blockRow + wm * 32 + m * 16 + g;
            if (r < N) {
                float2 v;
                v.x = fmaxf(c[m][nt][0] * s0 + t0, 0.f);
                v.y = fmaxf(c[m][nt][1] * s1 + t1, 0.f);
                *(float2*)(out + (size_t)r * 128 + col0) = v;
            }
            int r2 = r + 8;
            if (r2 < N) {
                float2 v;
                v.x = fmaxf(c[m][nt][2] * s0 + t0, 0.f);
                v.y = fmaxf(c[m][nt][3] * s1 + t1, 0.f);
                *(float2*)(out + (size_t)r2 * 128 + col0) = v;
            }
        }
    }
}

// GEMM2: K=128; cols 0..63 -> p = h@W2l^T (wn==0), cols 64..127 -> out = h@W2r^T + b2l (wn==1)
__global__ __launch_bounds__(256)
void gemm2_tf32(const float* __restrict__ h,
                const float* __restrict__ W2l,
                const float* __restrict__ W2r,
                const float* __restrict__ b2l,
                float* __restrict__ p_out,
                float* __restrict__ out, int N) {
    __shared__ float As[128 * GSTR];
    __shared__ float Ws[128 * GSTR];
    const int tid = threadIdx.x;
    const int lane = tid & 31, warp = tid >> 5;
    const int wm = warp & 3, wn = warp >> 2;
    const int g = lane >> 2, t = lane & 3;
    const int blockRow = blockIdx.x * 128;

    float c[2][8][4];
#pragma unroll
    for (int m = 0; m < 2; m++)
#pragma unroll
        for (int nt = 0; nt < 8; nt++)
#pragma unroll
            for (int q = 0; q < 4; q++) c[m][nt][q] = 0.f;

    for (int kt = 0; kt < 4; ++kt) {
        const int kloc = kt * 32;
#pragma unroll
        for (int p = 0; p < 4; ++p) {
            int idx = tid + p * 256;
            int row = idx >> 3, kq = (idx & 7) * 4;
            int n = blockRow + row;
            float4 v = make_float4(0.f, 0.f, 0.f, 0.f);
            if (n < N) v = *(const float4*)(h + (size_t)n * 128 + kloc + kq);
            *(float4*)&As[row * GSTR + kq] = cvt4(v);
        }
#pragma unroll
        for (int p = 0; p < 4; ++p) {
            int idx = tid + p * 256;
            int j = idx >> 3, kq = (idx & 7) * 4;
            const float* Wsrc = (j < 64) ? (W2l + (size_t)j * 128)
                                         : (W2r + (size_t)(j - 64) * 128);
            float4 v = *(const float4*)(Wsrc + kloc + kq);
            *(float4*)&Ws[j * GSTR + kq] = cvt4(v);
        }
        __syncthreads();

#pragma unroll
        for (int kc = 0; kc < 4; ++kc) {
            unsigned afr[2][4];
#pragma unroll
            for (int m = 0; m < 2; m++) {
                int r0 = wm * 32 + m * 16 + g;
                afr[m][0] = __float_as_uint(As[r0 * GSTR + kc * 8 + t]);
                afr[m][1] = __float_as_uint(As[(r0 + 8) * GSTR + kc * 8 + t]);
                afr[m][2] = __float_as_uint(As[r0 * GSTR + kc * 8 + t + 4]);
                afr[m][3] = __float_as_uint(As[(r0 + 8) * GSTR + kc * 8 + t + 4]);
            }
#pragma unroll
            for (int nt = 0; nt < 8; nt++) {
                int nrow = wn * 64 + nt * 8 + g;
                unsigned bfr[2] = {
                    __float_as_uint(Ws[nrow * GSTR + kc * 8 + t]),
                    __float_as_uint(Ws[nrow * GSTR + kc * 8 + t + 4])};
                mma16n8k8(c[0][nt], afr[0], bfr);
                mma16n8k8(c[1][nt], afr[1], bfr);
            }
        }
        __syncthreads();
    }

    if (wn == 0) {   // p output, cols 0..63, no bias
#pragma unroll
        for (int nt = 0; nt < 8; nt++) {
            int col0 = nt * 8 + 2 * t;
#pragma unroll
            for (int m = 0; m < 2; m++) {
                int r = blockRow + wm * 32 + m * 16 + g;
                if (r < N)
                    *(float2*)(p_out + (size_t)r * 64 + col0) =
                        make_float2(c[m][nt][0], c[m][nt][1]);
                int r2 = r + 8;
                if (r2 < N)
                    *(float2*)(p_out + (size_t)r2 * 64 + col0) =
                        make_float2(c[m][nt][2], c[m][nt][3]);
            }
        }
    } else {         // out, cols 64..127 -> out cols 0..63, + bias
#pragma unroll
        for (int nt = 0; nt < 8; nt++) {
            int col0 = nt * 8 + 2 * t;
            float b0 = b2l[col0], b1 = b2l[col0 + 1];
#pragma unroll
            for (int m = 0; m < 2; m++) {
                int r = blockRow + wm * 32 + m * 16 + g;
                if (r < N)
                    *(float2*)(out + (size_t)r * 64 + col0) =
                        make_float2(c[m][nt][0] + b0, c[m][nt][1] + b1);
                int r2 = r + 8;
                if (r2 < N)
                    *(float2*)(out + (size_t)r2 * 64 + col0) =
                        make_float2(c[m][nt][2] + b0, c[m][nt][3] + b1);
            }
        }
    }
}

// ---------------------------------------------------------------------------
extern "C" void kernel_launch(void* const* d_in, const int* in_sizes, int n_in,
                              void* d_out, int out_size) {
    const float* x        = (const float*)d_in[0];
    const int* ei         = (const int*)d_in[1];   // int32 (JAX x64 disabled)
    const float* W1l      = (const float*)d_in[2];
    const float* b1l      = (const float*)d_in[3];
    const float* W1r      = (const float*)d_in[4];
    const float* bn_gamma = (const float*)d_in[5];
    const float* bn_beta  = (const float*)d_in[6];
    const float* bn_mean  = (const float*)d_in[7];
    const float* bn_var   = (const float*)d_in[8];
    const float* W2l      = (const float*)d_in[9];
    const float* b2l      = (const float*)d_in[10];
    const float* W2r      = (const float*)d_in[11];
    float* out            = (float*)d_out;

    const int N = N_NODES_C;
    const int E = in_sizes[1] / 2;

    float *agg, *h, *p;
    int *deg, *rowstart, *cursor, *blocksum, *blockoff, *edge_src;
    cudaGetSymbolAddress((void**)&agg, g_agg);
    cudaGetSymbolAddress((void**)&h, g_h);
    cudaGetSymbolAddress((void**)&p, g_p);
    cudaGetSymbolAddress((void**)&deg, g_deg);
    cudaGetSymbolAddress((void**)&rowstart, g_rowstart);
    cudaGetSymbolAddress((void**)&cursor, g_cursor);
    cudaGetSymbolAddress((void**)&blocksum, g_blocksum);
    cudaGetSymbolAddress((void**)&blockoff, g_blockoff);
    cudaGetSymbolAddress((void**)&edge_src, g_edge_src);

    const int nb = (N + 1023) / 1024;   // 98 scan blocks

    // ---- CSR build (shared by both layers) ----
    cudaMemsetAsync(deg, 0, N * sizeof(int));
    hist_kernel<<<(E + 255) / 256, 256>>>(ei, E, deg);
    scan1_kernel<<<nb, 1024>>>(deg, rowstart, blocksum, N);
    scan2_kernel<<<1, 128>>>(blocksum, blockoff, nb);
    scan3_kernel<<<nb, 1024>>>(rowstart, cursor, blockoff, N);
    fill_kernel<<<(E + 255) / 256, 256>>>(ei, E, cursor, edge_src);

    // ---- Layer 1: agg = mean-gather(x); h = relu(bn(agg@W1l^T + x@W1r^T + b1l))
    {
        long long threads = (long long)N * 32;
        gather_kernel<32, false><<<(int)((threads + 255) / 256), 256>>>(
            (const float4*)x, rowstart, deg, edge_src, (float4*)agg, N);
    }
    gemm1_tf32<<<(N + 127) / 128, 256>>>(
        agg, x, W1l, W1r, b1l, bn_gamma, bn_beta, bn_mean, bn_var, h, N);

    // ---- Layer 2: p = h@W2l^T ; out = h@W2r^T + b2l ; out += mean-gather(p)
    gemm2_tf32<<<(N + 127) / 128, 256>>>(h, W2l, W2r, b2l, p, out, N);
    {
        long long threads = (long long)N * 16;
        gather_kernel<16, true><<<(int)((threads + 255) / 256), 256>>>(
            (const float4*)p, rowstart, deg, edge_src, (float4*)out, N);
    }
}

// round 11
// speedup vs baseline: 5.0134x; 1.0909x over previous
#include <cuda_runtime.h>

#define N_NODES_C 100000
#define E_MAX_C   1600000
#define BN_EPS 1e-5f

// Scratch (device globals — no allocation allowed)
__device__ float g_agg[(size_t)N_NODES_C * 128];
__device__ float g_h[(size_t)N_NODES_C * 128];
__device__ float g_p[(size_t)N_NODES_C * 64];
__device__ int   g_deg[N_NODES_C];
__device__ int   g_rowstart[N_NODES_C];
__device__ int   g_cursor[N_NODES_C];
__device__ int   g_blocksum[128];
__device__ int   g_blockoff[128];
__device__ int   g_edge_src[E_MAX_C];

// ---------------------------------------------------------------------------
// CSR construction
__global__ void hist_kernel(const int* __restrict__ ei, int E,
                            int* __restrict__ deg) {
    int e = blockIdx.x * blockDim.x + threadIdx.x;
    if (e < E) atomicAdd(&deg[ei[(size_t)E + e]], 1);
}

__global__ void scan1_kernel(const int* __restrict__ deg,
                             int* __restrict__ rowstart,
                             int* __restrict__ blocksum, int n) {
    __shared__ int s[1024];
    int tid = threadIdx.x;
    int i = blockIdx.x * 1024 + tid;
    int v = (i < n) ? deg[i] : 0;
    s[tid] = v;
    __syncthreads();
#pragma unroll
    for (int off = 1; off < 1024; off <<= 1) {
        int t = (tid >= off) ? s[tid - off] : 0;
        __syncthreads();
        s[tid] += t;
        __syncthreads();
    }
    if (i < n) rowstart[i] = s[tid] - v;          // local exclusive
    if (tid == 1023) blocksum[blockIdx.x] = s[tid];
}

__global__ void scan2_kernel(const int* __restrict__ blocksum,
                             int* __restrict__ blockoff, int nb) {
    __shared__ int s[128];
    int tid = threadIdx.x;
    int v = (tid < nb) ? blocksum[tid] : 0;
    s[tid] = v;
    __syncthreads();
#pragma unroll
    for (int off = 1; off < 128; off <<= 1) {
        int t = (tid >= off) ? s[tid - off] : 0;
        __syncthreads();
        s[tid] += t;
        __syncthreads();
    }
    if (tid < nb) blockoff[tid] = s[tid] - v;     // exclusive
}

__global__ void scan3_kernel(int* __restrict__ rowstart,
                             int* __restrict__ cursor,
                             const int* __restrict__ blockoff, int n) {
    int i = blockIdx.x * 1024 + threadIdx.x;
    if (i < n) {
        int r = rowstart[i] + blockoff[blockIdx.x];
        rowstart[i] = r;
        cursor[i] = r;
    }
}

__global__ void fill_kernel(const int* __restrict__ ei, int E,
                            int* __restrict__ cursor,
                            int* __restrict__ edge_src) {
    int e = blockIdx.x * blockDim.x + threadIdx.x;
    if (e < E) {
        int src = ei[e];
        int dst = ei[(size_t)E + e];
        int pos = atomicAdd(&cursor[dst], 1);
        edge_src[pos] = src;
    }
}

// ---------------------------------------------------------------------------
// Gather-aggregate: F4 threads per node (each lane owns one float4 of the row).
// 4-way unroll for MLP; dst = (sum feat[src]) / max(deg,1); optional +=.
template<int F4, bool ADD>
__global__ void gather_kernel(const float4* __restrict__ feat,
                              const int* __restrict__ rowstart,
                              const int* __restrict__ deg,
                              const int* __restrict__ edge_src,
                              float4* __restrict__ dstbuf, int N) {
    long long gid = (long long)blockIdx.x * blockDim.x + threadIdx.x;
    int n = (int)(gid / F4);
    if (n >= N) return;
    int lane = (int)(gid % F4);
    int d = deg[n];
    int start = rowstart[n];
    float4 acc = make_float4(0.f, 0.f, 0.f, 0.f);
    int j = 0;
    for (; j + 3 < d; j += 4) {
        int s0 = edge_src[start + j];
        int s1 = edge_src[start + j + 1];
        int s2 = edge_src[start + j + 2];
        int s3 = edge_src[start + j + 3];
        float4 a = feat[(size_t)s0 * F4 + lane];
        float4 b = feat[(size_t)s1 * F4 + lane];
        float4 cc = feat[(size_t)s2 * F4 + lane];
        float4 dd = feat[(size_t)s3 * F4 + lane];
        acc.x += (a.x + b.x) + (cc.x + dd.x);
        acc.y += (a.y + b.y) + (cc.y + dd.y);
        acc.z += (a.z + b.z) + (cc.z + dd.z);
        acc.w += (a.w + b.w) + (cc.w + dd.w);
    }
    for (; j < d; ++j) {
        float4 a = feat[(size_t)edge_src[start + j] * F4 + lane];
        acc.x += a.x; acc.y += a.y; acc.z += a.z; acc.w += a.w;
    }
    float inv = 1.0f / (float)max(d, 1);
    acc.x *= inv; acc.y *= inv; acc.z *= inv; acc.w *= inv;
    float4* p = &dstbuf[(size_t)n * F4 + lane];
    if (ADD) {
        float4 o = *p;
        o.x += acc.x; o.y += acc.y; o.z += acc.z; o.w += acc.w;
        *p = o;
    } else {
        *p = acc;
    }
}

// ---------------------------------------------------------------------------
// TF32 tensor-core GEMM machinery
__device__ __forceinline__ float f2tf32(float f) {
    unsigned u;
    asm("cvt.rna.tf32.f32 %0, %1;" : "=r"(u) : "f"(f));
    return __uint_as_float(u);
}
__device__ __forceinline__ float4 cvt4(float4 v) {
    return make_float4(f2tf32(v.x), f2tf32(v.y), f2tf32(v.z), f2tf32(v.w));
}
__device__ __forceinline__ void mma16n8k8(float* c, const unsigned* a,
                                          const unsigned* b) {
    asm volatile(
        "mma.sync.aligned.m16n8k8.row.col.f32.tf32.tf32.f32 "
        "{%0,%1,%2,%3}, {%4,%5,%6,%7}, {%8,%9}, {%0,%1,%2,%3};"
        : "+f"(c[0]), "+f"(c[1]), "+f"(c[2]), "+f"(c[3])
        : "r"(a[0]), "r"(a[1]), "r"(a[2]), "r"(a[3]), "r"(b[0]), "r"(b[1]));
}

// Block tile 128x128, 8 warps (4M x 2N), warp tile 32x64, BK=32.
// Smem stride 36 floats -> fragment LDS bank = (4g+t) mod 32, conflict-free.
#define GSTR 36

// Shared compute core: one k-tile of MMAs from smem.
__device__ __forceinline__ void mma_tile(const float* As, const float* Ws,
                                         int wm, int wn, int g, int t,
                                         float c[2][8][4]) {
#pragma unroll
    for (int kc = 0; kc < 4; ++kc) {
        unsigned afr[2][4];
#pragma unroll
        for (int m = 0; m < 2; m++) {
            int r0 = wm * 32 + m * 16 + g;
            afr[m][0] = __float_as_uint(As[r0 * GSTR + kc * 8 + t]);
            afr[m][1] = __float_as_uint(As[(r0 + 8) * GSTR + kc * 8 + t]);
            afr[m][2] = __float_as_uint(As[r0 * GSTR + kc * 8 + t + 4]);
            afr[m][3] = __float_as_uint(As[(r0 + 8) * GSTR + kc * 8 + t + 4]);
        }
#pragma unroll
        for (int nt = 0; nt < 8; nt++) {
            int nrow = wn * 64 + nt * 8 + g;
            unsigned bfr[2] = {
                __float_as_uint(Ws[nrow * GSTR + kc * 8 + t]),
                __float_as_uint(Ws[nrow * GSTR + kc * 8 + t + 4])};
            mma16n8k8(c[0][nt], afr[0], bfr);
            mma16n8k8(c[1][nt], afr[1], bfr);
        }
    }
}

// GEMM1: h = relu(bn( [agg | x] @ [W1l;W1r]^T + b1l )), K=256
__global__ __launch_bounds__(256)
void gemm1_tf32(const float* __restrict__ agg,
                const float* __restrict__ x2,
                const float* __restrict__ Wl,
                const float* __restrict__ Wr,
                const float* __restrict__ bias,
                const float* __restrict__ gamma,
                const float* __restrict__ beta,
                const float* __restrict__ mean,
                const float* __restrict__ var,
                float* __restrict__ out, int N) {
    __shared__ float As[128 * GSTR];
    __shared__ float Ws[128 * GSTR];
    const int tid = threadIdx.x;
    const int lane = tid & 31, warp = tid >> 5;
    const int wm = warp & 3, wn = warp >> 2;
    const int g = lane >> 2, t = lane & 3;
    const int blockRow = blockIdx.x * 128;
    const int arow = tid >> 3, akq = (tid & 7) * 4;  // this thread's 4-load slot base

    float c[2][8][4];
#pragma unroll
    for (int m = 0; m < 2; m++)
#pragma unroll
        for (int nt = 0; nt < 8; nt++)
#pragma unroll
            for (int q = 0; q < 4; q++) c[m][nt][q] = 0.f;

    float4 va[4], vw[4];
    auto loadRegs = [&](int kt) {
        const float* Asrc = (kt < 4) ? agg : x2;
        const float* Wsrc = (kt < 4) ? Wl : Wr;
        const int kloc = (kt & 3) * 32;
#pragma unroll
        for (int p = 0; p < 4; ++p) {
            int row = arow + p * 32;
            int n = blockRow + row;
            va[p] = make_float4(0.f, 0.f, 0.f, 0.f);
            if (n < N) va[p] = *(const float4*)(Asrc + (size_t)n * 128 + kloc + akq);
            vw[p] = *(const float4*)(Wsrc + (size_t)row * 128 + kloc + akq);
        }
    };
    auto storeSmem = [&]() {
#pragma unroll
        for (int p = 0; p < 4; ++p) {
            int row = arow + p * 32;
            *(float4*)&As[row * GSTR + akq] = cvt4(va[p]);
            *(float4*)&Ws[row * GSTR + akq] = cvt4(vw[p]);
        }
    };

    loadRegs(0);
    storeSmem();
    __syncthreads();
    for (int kt = 0; kt < 8; ++kt) {
        if (kt < 7) loadRegs(kt + 1);      // prefetch overlaps with MMA below
        mma_tile(As, Ws, wm, wn, g, t, c);
        __syncthreads();
        if (kt < 7) {
            storeSmem();
            __syncthreads();
        }
    }

#pragma unroll
    for (int nt = 0; nt < 8; nt++) {
        int col0 = wn * 64 + nt * 8 + 2 * t;
        float s0 = gamma[col0] * rsqrtf(var[col0] + BN_EPS);
        float s1 = gamma[col0 + 1] * rsqrtf(var[col0 + 1] + BN_EPS);
        float t0 = beta[col0] - mean[col0] * s0 + bias[col0] * s0;
        float t1 = beta[col0 + 1] - mean[col0 + 1] * s1 + bias[col0 + 1] * s1;
#pragma unroll
        for (int m = 0; m < 2; m++) {
            int r = blockRow + wm * 32 + m * 16 + g;
            if (r < N) {
                float2 v;
                v.x = fmaxf(c[m][nt][0] * s0 + t0, 0.f);
                v.y = fmaxf(c[m][nt][1] * s1 + t1, 0.f);
                *(float2*)(out + (size_t)r * 128 + col0) = v;
            }
            int r2 = r + 8;
            if (r2 < N) {
                float2 v;
                v.x = fmaxf(c[m][nt][2] * s0 + t0, 0.f);
                v.y = fmaxf(c[m][nt][3] * s1 + t1, 0.f);
                *(float2*)(out + (size_t)r2 * 128 + col0) = v;
            }
        }
    }
}

// GEMM2: K=128; cols 0..63 -> p = h@W2l^T (wn==0), cols 64..127 -> out = h@W2r^T + b2l (wn==1)
__global__ __launch_bounds__(256)
void gemm2_tf32(const float* __restrict__ h,
                const float* __restrict__ W2l,
                const float* __restrict__ W2r,
                const float* __restrict__ b2l,
                float* __restrict__ p_out,
                float* __restrict__ out, int N) {
    __shared__ float As[128 * GSTR];
    __shared__ float Ws[128 * GSTR];
    const int tid = threadIdx.x;
    const int lane = tid & 31, warp = tid >> 5;
    const int wm = warp & 3, wn = warp >> 2;
    const int g = lane >> 2, t = lane & 3;
    const int blockRow = blockIdx.x * 128;
    const int arow = tid >> 3, akq = (tid & 7) * 4;

    float c[2][8][4];
#pragma unroll
    for (int m = 0; m < 2; m++)
#pragma unroll
        for (int nt = 0; nt < 8; nt++)
#pragma unroll
            for (int q = 0; q < 4; q++) c[m][nt][q] = 0.f;

    float4 va[4], vw[4];
    auto loadRegs = [&](int kt) {
        const int kloc = kt * 32;
#pragma unroll
        for (int p = 0; p < 4; ++p) {
            int row = arow + p * 32;
            int n = blockRow + row;
            va[p] = make_float4(0.f, 0.f, 0.f, 0.f);
            if (n < N) va[p] = *(const float4*)(h + (size_t)n * 128 + kloc + akq);
            const float* Wsrc = (row < 64) ? (W2l + (size_t)row * 128)
                                           : (W2r + (size_t)(row - 64) * 128);
            vw[p] = *(const float4*)(Wsrc + kloc + akq);
        }
    };
    auto storeSmem = [&]() {
#pragma unroll
        for (int p = 0; p < 4; ++p) {
            int row = arow + p * 32;
            *(float4*)&As[row * GSTR + akq] = cvt4(va[p]);
            *(float4*)&Ws[row * GSTR + akq] = cvt4(vw[p]);
        }
    };

    loadRegs(0);
    storeSmem();
    __syncthreads();
    for (int kt = 0; kt < 4; ++kt) {
        if (kt < 3) loadRegs(kt + 1);
        mma_tile(As, Ws, wm, wn, g, t, c);
        __syncthreads();
        if (kt < 3) {
            storeSmem();
            __syncthreads();
        }
    }

    if (wn == 0) {   // p output, cols 0..63, no bias
#pragma unroll
        for (int nt = 0; nt < 8; nt++) {
            int col0 = nt * 8 + 2 * t;
#pragma unroll
            for (int m = 0; m < 2; m++) {
                int r = blockRow + wm * 32 + m * 16 + g;
                if (r < N)
                    *(float2*)(p_out + (size_t)r * 64 + col0) =
                        make_float2(c[m][nt][0], c[m][nt][1]);
                int r2 = r + 8;
                if (r2 < N)
                    *(float2*)(p_out + (size_t)r2 * 64 + col0) =
                        make_float2(c[m][nt][2], c[m][nt][3]);
            }
        }
    } else {         // out, cols 64..127 -> out cols 0..63, + bias
#pragma unroll
        for (int nt = 0; nt < 8; nt++) {
            int col0 = nt * 8 + 2 * t;
            float b0 = b2l[col0], b1 = b2l[col0 + 1];
#pragma unroll
            for (int m = 0; m < 2; m++) {
                int r = blockRow + wm * 32 + m * 16 + g;
                if (r < N)
                    *(float2*)(out + (size_t)r * 64 + col0) =
                        make_float2(c[m][nt][0] + b0, c[m][nt][1] + b1);
                int r2 = r + 8;
                if (r2 < N)
                    *(float2*)(out + (size_t)r2 * 64 + col0) =
                        make_float2(c[m][nt][2] + b0, c[m][nt][3] + b1);
            }
        }
    }
}

// ---------------------------------------------------------------------------
extern "C" void kernel_launch(void* const* d_in, const int* in_sizes, int n_in,
                              void* d_out, int out_size) {
    const float* x        = (const float*)d_in[0];
    const int* ei         = (const int*)d_in[1];   // int32 (JAX x64 disabled)
    const float* W1l      = (const float*)d_in[2];
    const float* b1l      = (const float*)d_in[3];
    const float* W1r      = (const float*)d_in[4];
    const float* bn_gamma = (const float*)d_in[5];
    const float* bn_beta  = (const float*)d_in[6];
    const float* bn_mean  = (const float*)d_in[7];
    const float* bn_var   = (const float*)d_in[8];
    const float* W2l      = (const float*)d_in[9];
    const float* b2l      = (const float*)d_in[10];
    const float* W2r      = (const float*)d_in[11];
    float* out            = (float*)d_out;

    const int N = N_NODES_C;
    const int E = in_sizes[1] / 2;

    float *agg, *h, *p;
    int *deg, *rowstart, *cursor, *blocksum, *blockoff, *edge_src;
    cudaGetSymbolAddress((void**)&agg, g_agg);
    cudaGetSymbolAddress((void**)&h, g_h);
    cudaGetSymbolAddress((void**)&p, g_p);
    cudaGetSymbolAddress((void**)&deg, g_deg);
    cudaGetSymbolAddress((void**)&rowstart, g_rowstart);
    cudaGetSymbolAddress((void**)&cursor, g_cursor);
    cudaGetSymbolAddress((void**)&blocksum, g_blocksum);
    cudaGetSymbolAddress((void**)&blockoff, g_blockoff);
    cudaGetSymbolAddress((void**)&edge_src, g_edge_src);

    const int nb = (N + 1023) / 1024;   // 98 scan blocks

    // ---- CSR build (shared by both layers) ----
    cudaMemsetAsync(deg, 0, N * sizeof(int));
    hist_kernel<<<(E + 255) / 256, 256>>>(ei, E, deg);
    scan1_kernel<<<nb, 1024>>>(deg, rowstart, blocksum, N);
    scan2_kernel<<<1, 128>>>(blocksum, blockoff, nb);
    scan3_kernel<<<nb, 1024>>>(rowstart, cursor, blockoff, N);
    fill_kernel<<<(E + 255) / 256, 256>>>(ei, E, cursor, edge_src);

    // ---- Layer 1: agg = mean-gather(x); h = relu(bn(agg@W1l^T + x@W1r^T + b1l))
    {
        long long threads = (long long)N * 32;
        gather_kernel<32, false><<<(int)((threads + 255) / 256), 256>>>(
            (const float4*)x, rowstart, deg, edge_src, (float4*)agg, N);
    }
    gemm1_tf32<<<(N + 127) / 128, 256>>>(
        agg, x, W1l, W1r, b1l, bn_gamma, bn_beta, bn_mean, bn_var, h, N);

    // ---- Layer 2: p = h@W2l^T ; out = h@W2r^T + b2l ; out += mean-gather(p)
    gemm2_tf32<<<(N + 127) / 128, 256>>>(h, W2l, W2r, b2l, p, out, N);
    {
        long long threads = (long long)N * 16;
        gather_kernel<16, true><<<(int)((threads + 255) / 256), 256>>>(
            (const float4*)p, rowstart, deg, edge_src, (float4*)out, N);
    }
}

// round 13
// speedup vs baseline: 5.4898x; 1.0950x over previous
#include <cuda_runtime.h>
#include <cuda_fp16.h>

#define N_NODES_C 100000
#define E_MAX_C   1600000
#define BN_EPS 1e-5f

// Scratch (device globals — no allocation allowed)
__device__ float  g_agg[(size_t)N_NODES_C * 128];
__device__ float  g_h[(size_t)N_NODES_C * 128];
__device__ __half g_x16[(size_t)N_NODES_C * 128];
__device__ __half g_p16[(size_t)N_NODES_C * 64];
__device__ int    g_deg[N_NODES_C];
__device__ int    g_rowstart[N_NODES_C];
__device__ int    g_cursor[N_NODES_C];
__device__ int    g_blocksum[128];
__device__ int    g_blockoff[128];
__device__ int    g_edge_src[E_MAX_C];

// ---------------------------------------------------------------------------
// CSR construction
__global__ void hist_kernel(const int* __restrict__ ei, int E,
                            int* __restrict__ deg) {
    int e = blockIdx.x * blockDim.x + threadIdx.x;
    if (e < E) atomicAdd(&deg[ei[(size_t)E + e]], 1);
}

__global__ void scan1_kernel(const int* __restrict__ deg,
                             int* __restrict__ rowstart,
                             int* __restrict__ blocksum, int n) {
    __shared__ int s[1024];
    int tid = threadIdx.x;
    int i = blockIdx.x * 1024 + tid;
    int v = (i < n) ? deg[i] : 0;
    s[tid] = v;
    __syncthreads();
#pragma unroll
    for (int off = 1; off < 1024; off <<= 1) {
        int t = (tid >= off) ? s[tid - off] : 0;
        __syncthreads();
        s[tid] += t;
        __syncthreads();
    }
    if (i < n) rowstart[i] = s[tid] - v;          // local exclusive
    if (tid == 1023) blocksum[blockIdx.x] = s[tid];
}

__global__ void scan2_kernel(const int* __restrict__ blocksum,
                             int* __restrict__ blockoff, int nb) {
    __shared__ int s[128];
    int tid = threadIdx.x;
    int v = (tid < nb) ? blocksum[tid] : 0;
    s[tid] = v;
    __syncthreads();
#pragma unroll
    for (int off = 1; off < 128; off <<= 1) {
        int t = (tid >= off) ? s[tid - off] : 0;
        __syncthreads();
        s[tid] += t;
        __syncthreads();
    }
    if (tid < nb) blockoff[tid] = s[tid] - v;     // exclusive
}

__global__ void scan3_kernel(int* __restrict__ rowstart,
                             int* __restrict__ cursor,
                             const int* __restrict__ blockoff, int n) {
    int i = blockIdx.x * 1024 + threadIdx.x;
    if (i < n) {
        int r = rowstart[i] + blockoff[blockIdx.x];
        rowstart[i] = r;
        cursor[i] = r;
    }
}

__global__ void fill_kernel(const int* __restrict__ ei, int E,
                            int* __restrict__ cursor,
                            int* __restrict__ edge_src) {
    int e = blockIdx.x * blockDim.x + threadIdx.x;
    if (e < E) {
        int src = ei[e];
        int dst = ei[(size_t)E + e];
        int pos = atomicAdd(&cursor[dst], 1);
        edge_src[pos] = src;
    }
}

// ---------------------------------------------------------------------------
// fp32 -> fp16 conversion: 8 elements per thread
__global__ void cvt_fp16_kernel(const float4* __restrict__ src,
                                uint4* __restrict__ dst, int n8) {
    int i = blockIdx.x * blockDim.x + threadIdx.x;
    if (i >= n8) return;
    float4 a = src[i * 2];
    float4 b = src[i * 2 + 1];
    __half2 h0 = __floats2half2_rn(a.x, a.y);
    __half2 h1 = __floats2half2_rn(a.z, a.w);
    __half2 h2 = __floats2half2_rn(b.x, b.y);
    __half2 h3 = __floats2half2_rn(b.z, b.w);
    uint4 o;
    o.x = *(unsigned*)&h0;
    o.y = *(unsigned*)&h1;
    o.z = *(unsigned*)&h2;
    o.w = *(unsigned*)&h3;
    dst[i] = o;
}

// ---------------------------------------------------------------------------
// fp16-payload gather: LANES threads per node; each lane owns 8 halves (16 B).
// acc fp32; result = mean over edges; ADD -> accumulate into fp32 dstbuf.
template<int LANES, bool ADD>
__global__ void gather16_kernel(const uint4* __restrict__ feat16,  // rows of LANES*8 halves
                                const int* __restrict__ rowstart,
                                const int* __restrict__ deg,
                                const int* __restrict__ edge_src,
                                float* __restrict__ dstbuf, int N) {
    long long gid = (long long)blockIdx.x * blockDim.x + threadIdx.x;
    int n = (int)(gid / LANES);
    if (n >= N) return;
    int lane = (int)(gid % LANES);
    int d = deg[n];
    int start = rowstart[n];
    float acc[8] = {0.f, 0.f, 0.f, 0.f, 0.f, 0.f, 0.f, 0.f};

    auto accum = [&](uint4 u) {
        __half2 h0 = *(__half2*)&u.x, h1 = *(__half2*)&u.y;
        __half2 h2 = *(__half2*)&u.z, h3 = *(__half2*)&u.w;
        float2 f0 = __half22float2(h0), f1 = __half22float2(h1);
        float2 f2 = __half22float2(h2), f3 = __half22float2(h3);
        acc[0] += f0.x; acc[1] += f0.y; acc[2] += f1.x; acc[3] += f1.y;
        acc[4] += f2.x; acc[5] += f2.y; acc[6] += f3.x; acc[7] += f3.y;
    };

    int j = 0;
    for (; j + 3 < d; j += 4) {
        int s0 = edge_src[start + j];
        int s1 = edge_src[start + j + 1];
        int s2 = edge_src[start + j + 2];
        int s3 = edge_src[start + j + 3];
        uint4 u0 = feat16[(size_t)s0 * LANES + lane];
        uint4 u1 = feat16[(size_t)s1 * LANES + lane];
        uint4 u2 = feat16[(size_t)s2 * LANES + lane];
        uint4 u3 = feat16[(size_t)s3 * LANES + lane];
        accum(u0); accum(u1); accum(u2); accum(u3);
    }
    for (; j < d; ++j)
        accum(feat16[(size_t)edge_src[start + j] * LANES + lane]);

    float inv = 1.0f / (float)max(d, 1);
    float* p = dstbuf + (size_t)n * (LANES * 8) + lane * 8;
    if (ADD) {
        float4 o0 = *(float4*)p, o1 = *(float4*)(p + 4);
        o0.x += acc[0] * inv; o0.y += acc[1] * inv;
        o0.z += acc[2] * inv; o0.w += acc[3] * inv;
        o1.x += acc[4] * inv; o1.y += acc[5] * inv;
        o1.z += acc[6] * inv; o1.w += acc[7] * inv;
        *(float4*)p = o0; *(float4*)(p + 4) = o1;
    } else {
        *(float4*)p = make_float4(acc[0] * inv, acc[1] * inv,
                                  acc[2] * inv, acc[3] * inv);
        *(float4*)(p + 4) = make_float4(acc[4] * inv, acc[5] * inv,
                                        acc[6] * inv, acc[7] * inv);
    }
}

// ---------------------------------------------------------------------------
// TF32 tensor-core GEMM machinery
__device__ __forceinline__ float f2tf32(float f) {
    unsigned u;
    asm("cvt.rna.tf32.f32 %0, %1;" : "=r"(u) : "f"(f));
    return __uint_as_float(u);
}
__device__ __forceinline__ float4 cvt4(float4 v) {
    return make_float4(f2tf32(v.x), f2tf32(v.y), f2tf32(v.z), f2tf32(v.w));
}
__device__ __forceinline__ void mma16n8k8(float* c, const unsigned* a,
                                          const unsigned* b) {
    asm volatile(
        "mma.sync.aligned.m16n8k8.row.col.f32.tf32.tf32.f32 "
        "{%0,%1,%2,%3}, {%4,%5,%6,%7}, {%8,%9}, {%0,%1,%2,%3};"
        : "+f"(c[0]), "+f"(c[1]), "+f"(c[2]), "+f"(c[3])
        : "r"(a[0]), "r"(a[1]), "r"(a[2]), "r"(a[3]), "r"(b[0]), "r"(b[1]));
}

#define GSTR 36

__device__ __forceinline__ void mma_tile(const float* As, const float* Ws,
                                         int wm, int wn, int g, int t,
                                         float c[2][8][4]) {
#pragma unroll
    for (int kc = 0; kc < 4; ++kc) {
        unsigned afr[2][4];
#pragma unroll
        for (int m = 0; m < 2; m++) {
            int r0 = wm * 32 + m * 16 + g;
            afr[m][0] = __float_as_uint(As[r0 * GSTR + kc * 8 + t]);
            afr[m][1] = __float_as_uint(As[(r0 + 8) * GSTR + kc * 8 + t]);
            afr[m][2] = __float_as_uint(As[r0 * GSTR + kc * 8 + t + 4]);
            afr[m][3] = __float_as_uint(As[(r0 + 8) * GSTR + kc * 8 + t + 4]);
        }
#pragma unroll
        for (int nt = 0; nt < 8; nt++) {
            int nrow = wn * 64 + nt * 8 + g;
            unsigned bfr[2] = {
                __float_as_uint(Ws[nrow * GSTR + kc * 8 + t]),
                __float_as_uint(Ws[nrow * GSTR + kc * 8 + t + 4])};
            mma16n8k8(c[0][nt], afr[0], bfr);
            mma16n8k8(c[1][nt], afr[1], bfr);
        }
    }
}

// GEMM1: h = relu(bn( [agg | x] @ [W1l;W1r]^T + b1l )), K=256
__global__ __launch_bounds__(256)
void gemm1_tf32(const float* __restrict__ agg,
                const float* __restrict__ x2,
                const float* __restrict__ Wl,
                const float* __restrict__ Wr,
                const float* __restrict__ bias,
                const float* __restrict__ gamma,
                const float* __restrict__ beta,
                const float* __restrict__ mean,
                const float* __restrict__ var,
                float* __restrict__ out, int N) {
    __shared__ float As[128 * GSTR];
    __shared__ float Ws[128 * GSTR];
    const int tid = threadIdx.x;
    const int lane = tid & 31, warp = tid >> 5;
    const int wm = warp & 3, wn = warp >> 2;
    const int g = lane >> 2, t = lane & 3;
    const int blockRow = blockIdx.x * 128;
    const int arow = tid >> 3, akq = (tid & 7) * 4;

    float c[2][8][4];
#pragma unroll
    for (int m = 0; m < 2; m++)
#pragma unroll
        for (int nt = 0; nt < 8; nt++)
#pragma unroll
            for (int q = 0; q < 4; q++) c[m][nt][q] = 0.f;

    float4 va[4], vw[4];
    auto loadRegs = [&](int kt) {
        const float* Asrc = (kt < 4) ? agg : x2;
        const float* Wsrc = (kt < 4) ? Wl : Wr;
        const int kloc = (kt & 3) * 32;
#pragma unroll
        for (int p = 0; p < 4; ++p) {
            int row = arow + p * 32;
            int n = blockRow + row;
            va[p] = make_float4(0.f, 0.f, 0.f, 0.f);
            if (n < N) va[p] = *(const float4*)(Asrc + (size_t)n * 128 + kloc + akq);
            vw[p] = *(const float4*)(Wsrc + (size_t)row * 128 + kloc + akq);
        }
    };
    auto storeSmem = [&]() {
#pragma unroll
        for (int p = 0; p < 4; ++p) {
            int row = arow + p * 32;
            *(float4*)&As[row * GSTR + akq] = cvt4(va[p]);
            *(float4*)&Ws[row * GSTR + akq] = cvt4(vw[p]);
        }
    };

    loadRegs(0);
    storeSmem();
    __syncthreads();
    for (int kt = 0; kt < 8; ++kt) {
        if (kt < 7) loadRegs(kt + 1);
        mma_tile(As, Ws, wm, wn, g, t, c);
        __syncthreads();
        if (kt < 7) {
            storeSmem();
            __syncthreads();
        }
    }

#pragma unroll
    for (int nt = 0; nt < 8; nt++) {
        int col0 = wn * 64 + nt * 8 + 2 * t;
        float s0 = gamma[col0] * rsqrtf(var[col0] + BN_EPS);
        float s1 = gamma[col0 + 1] * rsqrtf(var[col0 + 1] + BN_EPS);
        float t0 = beta[col0] - mean[col0] * s0 + bias[col0] * s0;
        float t1 = beta[col0 + 1] - mean[col0 + 1] * s1 + bias[col0 + 1] * s1;
#pragma unroll
        for (int m = 0; m < 2; m++) {
            int r = blockRow + wm * 32 + m * 16 + g;
            if (r < N) {
                float2 v;
                v.x = fmaxf(c[m][nt][0] * s0 + t0, 0.f);
                v.y = fmaxf(c[m][nt][1] * s1 + t1, 0.f);
                *(float2*)(out + (size_t)r * 128 + col0) = v;
            }
            int r2 = r + 8;
            if (r2 < N) {
                float2 v;
                v.x = fmaxf(c[m][nt][2] * s0 + t0, 0.f);
                v.y = fmaxf(c[m][nt][3] * s1 + t1, 0.f);
                *(float2*)(out + (size_t)r2 * 128 + col0) = v;
            }
        }
    }
}

// GEMM2: K=128; wn==0 -> p16 = fp16(h@W2l^T); wn==1 -> out = h@W2r^T + b2l
__global__ __launch_bounds__(256)
void gemm2_tf32(const float* __restrict__ h,
                const float* __restrict__ W2l,
                const float* __restrict__ W2r,
                const float* __restrict__ b2l,
                __half* __restrict__ p16,
                float* __restrict__ out, int N) {
    __shared__ float As[128 * GSTR];
    __shared__ float Ws[128 * GSTR];
    const int tid = threadIdx.x;
    const int lane = tid & 31, warp = tid >> 5;
    const int wm = warp & 3, wn = warp >> 2;
    const int g = lane >> 2, t = lane & 3;
    const int blockRow = blockIdx.x * 128;
    const int arow = tid >> 3, akq = (tid & 7) * 4;

    float c[2][8][4];
#pragma unroll
    for (int m = 0; m < 2; m++)
#pragma unroll
        for (int nt = 0; nt < 8; nt++)
#pragma unroll
            for (int q = 0; q < 4; q++) c[m][nt][q] = 0.f;

    float4 va[4], vw[4];
    auto loadRegs = [&](int kt) {
        const int kloc = kt * 32;
#pragma unroll
        for (int p = 0; p < 4; ++p) {
            int row = arow + p * 32;
            int n = blockRow + row;
            va[p] = make_float4(0.f, 0.f, 0.f, 0.f);
            if (n < N) va[p] = *(const float4*)(h + (size_t)n * 128 + kloc + akq);
            const float* Wsrc = (row < 64) ? (W2l + (size_t)row * 128)
                                           : (W2r + (size_t)(row - 64) * 128);
            vw[p] = *(const float4*)(Wsrc + kloc + akq);
        }
    };
    auto storeSmem = [&]() {
#pragma unroll
        for (int p = 0; p < 4; ++p) {
            int row = arow + p * 32;
            *(float4*)&As[row * GSTR + akq] = cvt4(va[p]);
            *(float4*)&Ws[row * GSTR + akq] = cvt4(vw[p]);
        }
    };

    loadRegs(0);
    storeSmem();
    __syncthreads();
    for (int kt = 0; kt < 4; ++kt) {
        if (kt < 3) loadRegs(kt + 1);
        mma_tile(As, Ws, wm, wn, g, t, c);
        __syncthreads();
        if (kt < 3) {
            storeSmem();
            __syncthreads();
        }
    }

    if (wn == 0) {   // p16 output, cols 0..63, no bias
#pragma unroll
        for (int nt = 0; nt < 8; nt++) {
            int col0 = nt * 8 + 2 * t;
#pragma unroll
            for (int m = 0; m < 2; m++) {
                int r = blockRow + wm * 32 + m * 16 + g;
                if (r < N) {
                    __half2 v = __floats2half2_rn(c[m][nt][0], c[m][nt][1]);
                    *(__half2*)(p16 + (size_t)r * 64 + col0) = v;
                }
                int r2 = r + 8;
                if (r2 < N) {
                    __half2 v = __floats2half2_rn(c[m][nt][2], c[m][nt][3]);
                    *(__half2*)(p16 + (size_t)r2 * 64 + col0) = v;
                }
            }
        }
    } else {         // out, + bias
#pragma unroll
        for (int nt = 0; nt < 8; nt++) {
            int col0 = nt * 8 + 2 * t;
            float b0 = b2l[col0], b1 = b2l[col0 + 1];
#pragma unroll
            for (int m = 0; m < 2; m++) {
                int r = blockRow + wm * 32 + m * 16 + g;
                if (r < N)
                    *(float2*)(out + (size_t)r * 64 + col0) =
                        make_float2(c[m][nt][0] + b0, c[m][nt][1] + b1);
                int r2 = r + 8;
                if (r2 < N)
                    *(float2*)(out + (size_t)r2 * 64 + col0) =
                        make_float2(c[m][nt][2] + b0, c[m][nt][3] + b1);
            }
        }
    }
}

// ---------------------------------------------------------------------------
extern "C" void kernel_launch(void* const* d_in, const int* in_sizes, int n_in,
                              void* d_out, int out_size) {
    const float* x        = (const float*)d_in[0];
    const int* ei         = (const int*)d_in[1];   // int32 (JAX x64 disabled)
    const float* W1l      = (const float*)d_in[2];
    const float* b1l      = (const float*)d_in[3];
    const float* W1r      = (const float*)d_in[4];
    const float* bn_gamma = (const float*)d_in[5];
    const float* bn_beta  = (const float*)d_in[6];
    const float* bn_mean  = (const float*)d_in[7];
    const float* bn_var   = (const float*)d_in[8];
    const float* W2l      = (const float*)d_in[9];
    const float* b2l      = (const float*)d_in[10];
    const float* W2r      = (const float*)d_in[11];
    float* out            = (float*)d_out;

    const int N = N_NODES_C;
    const int E = in_sizes[1] / 2;

    float *agg, *h;
    __half *x16, *p16;
    int *deg, *rowstart, *cursor, *blocksum, *blockoff, *edge_src;
    cudaGetSymbolAddress((void**)&agg, g_agg);
    cudaGetSymbolAddress((void**)&h, g_h);
    cudaGetSymbolAddress((void**)&x16, g_x16);
    cudaGetSymbolAddress((void**)&p16, g_p16);
    cudaGetSymbolAddress((void**)&deg, g_deg);
    cudaGetSymbolAddress((void**)&rowstart, g_rowstart);
    cudaGetSymbolAddress((void**)&cursor, g_cursor);
    cudaGetSymbolAddress((void**)&blocksum, g_blocksum);
    cudaGetSymbolAddress((void**)&blockoff, g_blockoff);
    cudaGetSymbolAddress((void**)&edge_src, g_edge_src);

    const int nb = (N + 1023) / 1024;   // 98 scan blocks

    // ---- CSR build (shared by both layers) ----
    cudaMemsetAsync(deg, 0, N * sizeof(int));
    hist_kernel<<<(E + 255) / 256, 256>>>(ei, E, deg);
    scan1_kernel<<<nb, 1024>>>(deg, rowstart, blocksum, N);
    scan2_kernel<<<1, 128>>>(blocksum, blockoff, nb);
    scan3_kernel<<<nb, 1024>>>(rowstart, cursor, blockoff, N);
    fill_kernel<<<(E + 255) / 256, 256>>>(ei, E, cursor, edge_src);

    // ---- x -> fp16 copy for gather payload ----
    {
        int n8 = N * 128 / 8;   // 1.6M
        cvt_fp16_kernel<<<(n8 + 255) / 256, 256>>>(
            (const float4*)x, (uint4*)x16, n8);
    }

    // ---- Layer 1: agg = mean-gather16(x16); h = relu(bn(agg@W1l^T + x@W1r^T + b1l))
    {
        long long threads = (long long)N * 16;
        gather16_kernel<16, false><<<(int)((threads + 255) / 256), 256>>>(
            (const uint4*)x16, rowstart, deg, edge_src, agg, N);
    }
    gemm1_tf32<<<(N + 127) / 128, 256>>>(
        agg, x, W1l, W1r, b1l, bn_gamma, bn_beta, bn_mean, bn_var, h, N);

    // ---- Layer 2: p16 = fp16(h@W2l^T); out = h@W2r^T + b2l; out += mean-gather16(p16)
    gemm2_tf32<<<(N + 127) / 128, 256>>>(h, W2l, W2r, b2l, p16, out, N);
    {
        long long threads = (long long)N * 8;
        gather16_kernel<8, true><<<(int)((threads + 255) / 256), 256>>>(
            (const uint4*)p16, rowstart, deg, edge_src, out, N);
    }
}

// round 14
// speedup vs baseline: 6.4347x; 1.1721x over previous
#include <cuda_runtime.h>
#include <cuda_fp16.h>

#define N_NODES_C 100000
#define E_MAX_C   1600000
#define BN_EPS 1e-5f

// Scratch (device globals — no allocation allowed)
__device__ __half g_agg16[(size_t)N_NODES_C * 128];
__device__ __half g_h16[(size_t)N_NODES_C * 128];
__device__ __half g_x16[(size_t)N_NODES_C * 128];
__device__ __half g_p16[(size_t)N_NODES_C * 64];
__device__ int    g_deg[N_NODES_C];
__device__ int    g_rowstart[N_NODES_C];
__device__ int    g_cursor[N_NODES_C];
__device__ int    g_blocksum[128];
__device__ int    g_blockoff[128];
__device__ int    g_ticket[1];
__device__ int    g_edge_src[E_MAX_C];

// ---------------------------------------------------------------------------
// cvt x->fp16 AND zero deg (fused to drop one launch)
__global__ void cvt0_kernel(const float4* __restrict__ src,
                            uint4* __restrict__ dst, int n8,
                            int* __restrict__ deg, int N) {
    int i = blockIdx.x * blockDim.x + threadIdx.x;
    if (i < N) deg[i] = 0;
    if (i >= n8) return;
    float4 a = src[i * 2];
    float4 b = src[i * 2 + 1];
    __half2 h0 = __floats2half2_rn(a.x, a.y);
    __half2 h1 = __floats2half2_rn(a.z, a.w);
    __half2 h2 = __floats2half2_rn(b.x, b.y);
    __half2 h3 = __floats2half2_rn(b.z, b.w);
    uint4 o;
    o.x = *(unsigned*)&h0;
    o.y = *(unsigned*)&h1;
    o.z = *(unsigned*)&h2;
    o.w = *(unsigned*)&h3;
    dst[i] = o;
}

// hist + zero the scan ticket for this call
__global__ void hist_kernel(const int* __restrict__ ei, int E,
                            int* __restrict__ deg, int* __restrict__ ticket) {
    int e = blockIdx.x * blockDim.x + threadIdx.x;
    if (e == 0) *ticket = 0;
    if (e < E) atomicAdd(&deg[ei[(size_t)E + e]], 1);
}

// Fused scan1+scan2: per-block scan; last block to finish scans the block sums.
__global__ void scan12_kernel(const int* __restrict__ deg,
                              int* __restrict__ rowstart,
                              int* __restrict__ blocksum,
                              int* __restrict__ blockoff,
                              int* __restrict__ ticket, int n, int nb) {
    __shared__ int s[1024];
    __shared__ int isLast;
    int tid = threadIdx.x;
    int i = blockIdx.x * 1024 + tid;
    int v = (i < n) ? deg[i] : 0;
    s[tid] = v;
    __syncthreads();
#pragma unroll
    for (int off = 1; off < 1024; off <<= 1) {
        int t = (tid >= off) ? s[tid - off] : 0;
        __syncthreads();
        s[tid] += t;
        __syncthreads();
    }
    if (i < n) rowstart[i] = s[tid] - v;          // local exclusive
    if (tid == 1023) {
        blocksum[blockIdx.x] = s[tid];
        __threadfence();
    }
    __syncthreads();
    if (tid == 0) {
        int old = atomicAdd(ticket, 1);
        isLast = (old == nb - 1);
    }
    __syncthreads();
    if (isLast) {
        __threadfence();
        __shared__ int s2[128];
        int b = (tid < nb) ? ((volatile int*)blocksum)[tid] : 0;
        if (tid < 128) s2[tid] = b;
        __syncthreads();
#pragma unroll
        for (int off = 1; off < 128; off <<= 1) {
            int t = (tid < 128 && tid >= off) ? s2[tid - off] : 0;
            __syncthreads();
            if (tid < 128) s2[tid] += t;
            __syncthreads();
        }
        if (tid < nb) blockoff[tid] = s2[tid] - b;   // exclusive
    }
}

__global__ void scan3_kernel(int* __restrict__ rowstart,
                             int* __restrict__ cursor,
                             const int* __restrict__ blockoff, int n) {
    int i = blockIdx.x * 1024 + threadIdx.x;
    if (i < n) {
        int r = rowstart[i] + blockoff[blockIdx.x];
        rowstart[i] = r;
        cursor[i] = r;
    }
}

__global__ void fill_kernel(const int* __restrict__ ei, int E,
                            int* __restrict__ cursor,
                            int* __restrict__ edge_src) {
    int e = blockIdx.x * blockDim.x + threadIdx.x;
    if (e < E) {
        int src = ei[e];
        int dst = ei[(size_t)E + e];
        int pos = atomicAdd(&cursor[dst], 1);
        edge_src[pos] = src;
    }
}

// ---------------------------------------------------------------------------
// gather (fp16 payload, fp32 accumulate, fp16 output): LANES lanes per node.
template<int LANES>
__global__ void gather_to16_kernel(const uint4* __restrict__ feat16,
                                   const int* __restrict__ rowstart,
                                   const int* __restrict__ deg,
                                   const int* __restrict__ edge_src,
                                   uint4* __restrict__ dst16, int N) {
    long long gid = (long long)blockIdx.x * blockDim.x + threadIdx.x;
    int n = (int)(gid / LANES);
    if (n >= N) return;
    int lane = (int)(gid % LANES);
    int d = deg[n];
    int start = rowstart[n];
    float acc[8] = {0.f, 0.f, 0.f, 0.f, 0.f, 0.f, 0.f, 0.f};
    auto accum = [&](uint4 u) {
        float2 f0 = __half22float2(*(__half2*)&u.x);
        float2 f1 = __half22float2(*(__half2*)&u.y);
        float2 f2 = __half22float2(*(__half2*)&u.z);
        float2 f3 = __half22float2(*(__half2*)&u.w);
        acc[0] += f0.x; acc[1] += f0.y; acc[2] += f1.x; acc[3] += f1.y;
        acc[4] += f2.x; acc[5] += f2.y; acc[6] += f3.x; acc[7] += f3.y;
    };
    int j = 0;
    for (; j + 3 < d; j += 4) {
        int s0 = edge_src[start + j];
        int s1 = edge_src[start + j + 1];
        int s2 = edge_src[start + j + 2];
        int s3 = edge_src[start + j + 3];
        uint4 u0 = feat16[(size_t)s0 * LANES + lane];
        uint4 u1 = feat16[(size_t)s1 * LANES + lane];
        uint4 u2 = feat16[(size_t)s2 * LANES + lane];
        uint4 u3 = feat16[(size_t)s3 * LANES + lane];
        accum(u0); accum(u1); accum(u2); accum(u3);
    }
    for (; j < d; ++j)
        accum(feat16[(size_t)edge_src[start + j] * LANES + lane]);
    float inv = 1.0f / (float)max(d, 1);
    __half2 h0 = __floats2half2_rn(acc[0] * inv, acc[1] * inv);
    __half2 h1 = __floats2half2_rn(acc[2] * inv, acc[3] * inv);
    __half2 h2 = __floats2half2_rn(acc[4] * inv, acc[5] * inv);
    __half2 h3 = __floats2half2_rn(acc[6] * inv, acc[7] * inv);
    uint4 o;
    o.x = *(unsigned*)&h0; o.y = *(unsigned*)&h1;
    o.z = *(unsigned*)&h2; o.w = *(unsigned*)&h3;
    dst16[(size_t)n * LANES + lane] = o;
}

// gather (fp16 payload) accumulating into fp32 out
template<int LANES>
__global__ void gather_add32_kernel(const uint4* __restrict__ feat16,
                                    const int* __restrict__ rowstart,
                                    const int* __restrict__ deg,
                                    const int* __restrict__ edge_src,
                                    float* __restrict__ dstbuf, int N) {
    long long gid = (long long)blockIdx.x * blockDim.x + threadIdx.x;
    int n = (int)(gid / LANES);
    if (n >= N) return;
    int lane = (int)(gid % LANES);
    int d = deg[n];
    int start = rowstart[n];
    float acc[8] = {0.f, 0.f, 0.f, 0.f, 0.f, 0.f, 0.f, 0.f};
    auto accum = [&](uint4 u) {
        float2 f0 = __half22float2(*(__half2*)&u.x);
        float2 f1 = __half22float2(*(__half2*)&u.y);
        float2 f2 = __half22float2(*(__half2*)&u.z);
        float2 f3 = __half22float2(*(__half2*)&u.w);
        acc[0] += f0.x; acc[1] += f0.y; acc[2] += f1.x; acc[3] += f1.y;
        acc[4] += f2.x; acc[5] += f2.y; acc[6] += f3.x; acc[7] += f3.y;
    };
    int j = 0;
    for (; j + 3 < d; j += 4) {
        int s0 = edge_src[start + j];
        int s1 = edge_src[start + j + 1];
        int s2 = edge_src[start + j + 2];
        int s3 = edge_src[start + j + 3];
        uint4 u0 = feat16[(size_t)s0 * LANES + lane];
        uint4 u1 = feat16[(size_t)s1 * LANES + lane];
        uint4 u2 = feat16[(size_t)s2 * LANES + lane];
        uint4 u3 = feat16[(size_t)s3 * LANES + lane];
        accum(u0); accum(u1); accum(u2); accum(u3);
    }
    for (; j < d; ++j)
        accum(feat16[(size_t)edge_src[start + j] * LANES + lane]);
    float inv = 1.0f / (float)max(d, 1);
    float* p = dstbuf + (size_t)n * (LANES * 8) + lane * 8;
    float4 o0 = *(float4*)p, o1 = *(float4*)(p + 4);
    o0.x += acc[0] * inv; o0.y += acc[1] * inv;
    o0.z += acc[2] * inv; o0.w += acc[3] * inv;
    o1.x += acc[4] * inv; o1.y += acc[5] * inv;
    o1.z += acc[6] * inv; o1.w += acc[7] * inv;
    *(float4*)p = o0; *(float4*)(p + 4) = o1;
}

// ---------------------------------------------------------------------------
// fp16 tensor-core GEMM (m16n8k16, fp32 accumulate).
// Block 128x128, 8 warps (4M x 2N), warp tile 32x64, BK=32 halves.
// Smem stride 40 halves: fragment half2 load bank = (20g+t) mod 32 — conflict-free.
#define ASTRH 40

__device__ __forceinline__ void mma16n8k16(float* c, const unsigned* a,
                                           const unsigned* b) {
    asm volatile(
        "mma.sync.aligned.m16n8k16.row.col.f32.f16.f16.f32 "
        "{%0,%1,%2,%3}, {%4,%5,%6,%7}, {%8,%9}, {%0,%1,%2,%3};"
        : "+f"(c[0]), "+f"(c[1]), "+f"(c[2]), "+f"(c[3])
        : "r"(a[0]), "r"(a[1]), "r"(a[2]), "r"(a[3]), "r"(b[0]), "r"(b[1]));
}

__device__ __forceinline__ void mma_tile16(const __half* As, const __half* Ws,
                                           int wm, int wn, int g, int t,
                                           float c[2][8][4]) {
#pragma unroll
    for (int kc = 0; kc < 2; ++kc) {
        unsigned afr[2][4];
#pragma unroll
        for (int m = 0; m < 2; m++) {
            int r0 = wm * 32 + m * 16 + g;
            afr[m][0] = *(const unsigned*)&As[r0 * ASTRH + kc * 16 + 2 * t];
            afr[m][1] = *(const unsigned*)&As[(r0 + 8) * ASTRH + kc * 16 + 2 * t];
            afr[m][2] = *(const unsigned*)&As[r0 * ASTRH + kc * 16 + 8 + 2 * t];
            afr[m][3] = *(const unsigned*)&As[(r0 + 8) * ASTRH + kc * 16 + 8 + 2 * t];
        }
#pragma unroll
        for (int nt = 0; nt < 8; nt++) {
            int nrow = wn * 64 + nt * 8 + g;
            unsigned bfr[2] = {
                *(const unsigned*)&Ws[nrow * ASTRH + kc * 16 + 2 * t],
                *(const unsigned*)&Ws[nrow * ASTRH + kc * 16 + 8 + 2 * t]};
            mma16n8k16(c[0][nt], afr[0], bfr);
            mma16n8k16(c[1][nt], afr[1], bfr);
        }
    }
}

// GEMM1: h16 = relu(bn( [agg16 | x16] @ [W1l;W1r]^T + b1l )), K=256
__global__ __launch_bounds__(256)
void gemm1_f16(const __half* __restrict__ agg16,
               const __half* __restrict__ x16,
               const float* __restrict__ Wl,
               const float* __restrict__ Wr,
               const float* __restrict__ bias,
               const float* __restrict__ gamma,
               const float* __restrict__ beta,
               const float* __restrict__ mean,
               const float* __restrict__ var,
               __half* __restrict__ h16, int N) {
    __shared__ __half As[128 * ASTRH];
    __shared__ __half Ws[128 * ASTRH];
    const int tid = threadIdx.x;
    const int lane = tid & 31, warp = tid >> 5;
    const int wm = warp & 3, wn = warp >> 2;
    const int g = lane >> 2, t = lane & 3;
    const int blockRow = blockIdx.x * 128;
    const int arow = tid >> 2, aq = tid & 3;       // A: 4 uint4-slots per row
    const int wrow = tid >> 3, wq = tid & 7;       // W: 8 float4-slots per row (p-strided)

    float c[2][8][4];
#pragma unroll
    for (int m = 0; m < 2; m++)
#pragma unroll
        for (int nt = 0; nt < 8; nt++)
#pragma unroll
            for (int q = 0; q < 4; q++) c[m][nt][q] = 0.f;

    uint4 va[2];
    float4 vw[4];
    auto loadRegs = [&](int kt) {
        const __half* Asrc = (kt < 4) ? agg16 : x16;
        const float* Wsrc = (kt < 4) ? Wl : Wr;
        const int kloc = (kt & 3) * 32;
#pragma unroll
        for (int p = 0; p < 2; ++p) {
            int row = arow + p * 64;
            int n = blockRow + row;
            va[p] = make_uint4(0, 0, 0, 0);
            if (n < N)
                va[p] = *(const uint4*)(Asrc + (size_t)n * 128 + kloc + aq * 8);
        }
#pragma unroll
        for (int p = 0; p < 4; ++p) {
            int row = wrow + p * 32;
            vw[p] = *(const float4*)(Wsrc + (size_t)row * 128 + kloc + wq * 4);
        }
    };
    auto storeSmem = [&]() {
#pragma unroll
        for (int p = 0; p < 2; ++p) {
            int row = arow + p * 64;
            *(uint4*)&As[row * ASTRH + aq * 8] = va[p];
        }
#pragma unroll
        for (int p = 0; p < 4; ++p) {
            int row = wrow + p * 32;
            __half2 lo = __floats2half2_rn(vw[p].x, vw[p].y);
            __half2 hi = __floats2half2_rn(vw[p].z, vw[p].w);
            uint2 u = make_uint2(*(unsigned*)&lo, *(unsigned*)&hi);
            *(uint2*)&Ws[row * ASTRH + wq * 4] = u;
        }
    };

    loadRegs(0);
    storeSmem();
    __syncthreads();
    for (int kt = 0; kt < 8; ++kt) {
        if (kt < 7) loadRegs(kt + 1);
        mma_tile16(As, Ws, wm, wn, g, t, c);
        __syncthreads();
        if (kt < 7) {
            storeSmem();
            __syncthreads();
        }
    }

#pragma unroll
    for (int nt = 0; nt < 8; nt++) {
        int col0 = wn * 64 + nt * 8 + 2 * t;
        float s0 = gamma[col0] * rsqrtf(var[col0] + BN_EPS);
        float s1 = gamma[col0 + 1] * rsqrtf(var[col0 + 1] + BN_EPS);
        float t0 = beta[col0] - mean[col0] * s0 + bias[col0] * s0;
        float t1 = beta[col0 + 1] - mean[col0 + 1] * s1 + bias[col0 + 1] * s1;
#pragma unroll
        for (int m = 0; m < 2; m++) {
            int r = blockRow + wm * 32 + m * 16 + g;
            if (r < N) {
                __half2 v = __floats2half2_rn(fmaxf(c[m][nt][0] * s0 + t0, 0.f),
                                              fmaxf(c[m][nt][1] * s1 + t1, 0.f));
                *(__half2*)(h16 + (size_t)r * 128 + col0) = v;
            }
            int r2 = r + 8;
            if (r2 < N) {
                __half2 v = __floats2half2_rn(fmaxf(c[m][nt][2] * s0 + t0, 0.f),
                                              fmaxf(c[m][nt][3] * s1 + t1, 0.f));
                *(__half2*)(h16 + (size_t)r2 * 128 + col0) = v;
            }
        }
    }
}

// GEMM2: K=128; wn==0 -> p16 = fp16(h@W2l^T); wn==1 -> out = h@W2r^T + b2l
__global__ __launch_bounds__(256)
void gemm2_f16(const __half* __restrict__ h16,
               const float* __restrict__ W2l,
               const float* __restrict__ W2r,
               const float* __restrict__ b2l,
               __half* __restrict__ p16,
               float* __restrict__ out, int N) {
    __shared__ __half As[128 * ASTRH];
    __shared__ __half Ws[128 * ASTRH];
    const int tid = threadIdx.x;
    const int lane = tid & 31, warp = tid >> 5;
    const int wm = warp & 3, wn = warp >> 2;
    const int g = lane >> 2, t = lane & 3;
    const int blockRow = blockIdx.x * 128;
    const int arow = tid >> 2, aq = tid & 3;
    const int wrow = tid >> 3, wq = tid & 7;

    float c[2][8][4];
#pragma unroll
    for (int m = 0; m < 2; m++)
#pragma unroll
        for (int nt = 0; nt < 8; nt++)
#pragma unroll
            for (int q = 0; q < 4; q++) c[m][nt][q] = 0.f;

    uint4 va[2];
    float4 vw[4];
    auto loadRegs = [&](int kt) {
        const int kloc = kt * 32;
#pragma unroll
        for (int p = 0; p < 2; ++p) {
            int row = arow + p * 64;
            int n = blockRow + row;
            va[p] = make_uint4(0, 0, 0, 0);
            if (n < N)
                va[p] = *(const uint4*)(h16 + (size_t)n * 128 + kloc + aq * 8);
        }
#pragma unroll
        for (int p = 0; p < 4; ++p) {
            int row = wrow + p * 32;
            const float* Wsrc = (row < 64) ? (W2l + (size_t)row * 128)
                                           : (W2r + (size_t)(row - 64) * 128);
            vw[p] = *(const float4*)(Wsrc + kloc + wq * 4);
        }
    };
    auto storeSmem = [&]() {
#pragma unroll
        for (int p = 0; p < 2; ++p) {
            int row = arow + p * 64;
            *(uint4*)&As[row * ASTRH + aq * 8] = va[p];
        }
#pragma unroll
        for (int p = 0; p < 4; ++p) {
            int row = wrow + p * 32;
            __half2 lo = __floats2half2_rn(vw[p].x, vw[p].y);
            __half2 hi = __floats2half2_rn(vw[p].z, vw[p].w);
            uint2 u = make_uint2(*(unsigned*)&lo, *(unsigned*)&hi);
            *(uint2*)&Ws[row * ASTRH + wq * 4] = u;
        }
    };

    loadRegs(0);
    storeSmem();
    __syncthreads();
    for (int kt = 0; kt < 4; ++kt) {
        if (kt < 3) loadRegs(kt + 1);
        mma_tile16(As, Ws, wm, wn, g, t, c);
        __syncthreads();
        if (kt < 3) {
            storeSmem();
            __syncthreads();
        }
    }

    if (wn == 0) {   // p16, cols 0..63, no bias
#pragma unroll
        for (int nt = 0; nt < 8; nt++) {
            int col0 = nt * 8 + 2 * t;
#pragma unroll
            for (int m = 0; m < 2; m++) {
                int r = blockRow + wm * 32 + m * 16 + g;
                if (r < N) {
                    __half2 v = __floats2half2_rn(c[m][nt][0], c[m][nt][1]);
                    *(__half2*)(p16 + (size_t)r * 64 + col0) = v;
                }
                int r2 = r + 8;
                if (r2 < N) {
                    __half2 v = __floats2half2_rn(c[m][nt][2], c[m][nt][3]);
                    *(__half2*)(p16 + (size_t)r2 * 64 + col0) = v;
                }
            }
        }
    } else {         // out, + bias
#pragma unroll
        for (int nt = 0; nt < 8; nt++) {
            int col0 = nt * 8 + 2 * t;
            float b0 = b2l[col0], b1 = b2l[col0 + 1];
#pragma unroll
            for (int m = 0; m < 2; m++) {
                int r = blockRow + wm * 32 + m * 16 + g;
                if (r < N)
                    *(float2*)(out + (size_t)r * 64 + col0) =
                        make_float2(c[m][nt][0] + b0, c[m][nt][1] + b1);
                int r2 = r + 8;
                if (r2 < N)
                    *(float2*)(out + (size_t)r2 * 64 + col0) =
                        make_float2(c[m][nt][2] + b0, c[m][nt][3] + b1);
            }
        }
    }
}

// ---------------------------------------------------------------------------
extern "C" void kernel_launch(void* const* d_in, const int* in_sizes, int n_in,
                              void* d_out, int out_size) {
    const float* x        = (const float*)d_in[0];
    const int* ei         = (const int*)d_in[1];   // int32 (JAX x64 disabled)
    const float* W1l      = (const float*)d_in[2];
    const float* b1l      = (const float*)d_in[3];
    const float* W1r      = (const float*)d_in[4];
    const float* bn_gamma = (const float*)d_in[5];
    const float* bn_beta  = (const float*)d_in[6];
    const float* bn_mean  = (const float*)d_in[7];
    const float* bn_var   = (const float*)d_in[8];
    const float* W2l      = (const float*)d_in[9];
    const float* b2l      = (const float*)d_in[10];
    const float* W2r      = (const float*)d_in[11];
    float* out            = (float*)d_out;

    const int N = N_NODES_C;
    const int E = in_sizes[1] / 2;

    __half *agg16, *h16, *x16, *p16;
    int *deg, *rowstart, *cursor, *blocksum, *blockoff, *ticket, *edge_src;
    cudaGetSymbolAddress((void**)&agg16, g_agg16);
    cudaGetSymbolAddress((void**)&h16, g_h16);
    cudaGetSymbolAddress((void**)&x16, g_x16);
    cudaGetSymbolAddress((void**)&p16, g_p16);
    cudaGetSymbolAddress((void**)&deg, g_deg);
    cudaGetSymbolAddress((void**)&rowstart, g_rowstart);
    cudaGetSymbolAddress((void**)&cursor, g_cursor);
    cudaGetSymbolAddress((void**)&blocksum, g_blocksum);
    cudaGetSymbolAddress((void**)&blockoff, g_blockoff);
    cudaGetSymbolAddress((void**)&ticket, g_ticket);
    cudaGetSymbolAddress((void**)&edge_src, g_edge_src);

    const int nb = (N + 1023) / 1024;   // 98 scan blocks

    // 1) cvt x->fp16 + zero deg
    {
        int n8 = N * 128 / 8;   // 1.6M
        cvt0_kernel<<<(n8 + 255) / 256, 256>>>(
            (const float4*)x, (uint4*)x16, n8, deg, N);
    }
    // 2) histogram (+ticket reset)
    hist_kernel<<<(E + 255) / 256, 256>>>(ei, E, deg, ticket);
    // 3) fused block scan + blocksum scan
    scan12_kernel<<<nb, 1024>>>(deg, rowstart, blocksum, blockoff, ticket, N, nb);
    // 4) apply block offsets
    scan3_kernel<<<nb, 1024>>>(rowstart, cursor, blockoff, N);
    // 5) CSR fill
    fill_kernel<<<(E + 255) / 256, 256>>>(ei, E, cursor, edge_src);

    // 6) Layer 1 gather: agg16 = mean-gather(x16)   [profiled launch]
    {
        long long threads = (long long)N * 16;
        gather_to16_kernel<16><<<(int)((threads + 255) / 256), 256>>>(
            (const uint4*)x16, rowstart, deg, edge_src, (uint4*)agg16, N);
    }
    // 7) GEMM1 -> h16
    gemm1_f16<<<(N + 127) / 128, 256>>>(
        agg16, x16, W1l, W1r, b1l, bn_gamma, bn_beta, bn_mean, bn_var, h16, N);
    // 8) GEMM2 -> p16 + out
    gemm2_f16<<<(N + 127) / 128, 256>>>(h16, W2l, W2r, b2l, p16, out, N);
    // 9) Layer 2 gather: out += mean-gather(p16)
    {
        long long threads = (long long)N * 8;
        gather_add32_kernel<8><<<(int)((threads + 255) / 256), 256>>>(
            (const uint4*)p16, rowstart, deg, edge_src, out, N);
    }
}

// round 15
// speedup vs baseline: 6.6539x; 1.0341x over previous
#include <cuda_runtime.h>
#include <cuda_fp16.h>

#define N_NODES_C 100000
#define E_MAX_C   1600000
#define BN_EPS 1e-5f

// Scratch (device globals — no allocation allowed)
__device__ __half g_agg16[(size_t)N_NODES_C * 128];
__device__ __half g_h16[(size_t)N_NODES_C * 128];
__device__ __half g_x16[(size_t)N_NODES_C * 128];
__device__ __half g_p16[(size_t)N_NODES_C * 64];
__device__ int    g_deg[N_NODES_C];
__device__ int    g_rowstart[N_NODES_C];   // local-exclusive (within scan block)
__device__ int    g_cursor[N_NODES_C];     // local-exclusive copy for fill
__device__ int    g_blocksum[128];
__device__ int    g_blockoff[128];
__device__ int    g_ticket[1];
__device__ int    g_edge_src[E_MAX_C];

// ---------------------------------------------------------------------------
// Fused: x->fp16 conversion + degree histogram (+ticket reset).
// deg must be zeroed beforehand (memsetAsync).
__global__ void cvthist_kernel(const float4* __restrict__ src,
                               uint4* __restrict__ dst, int n8,
                               const int* __restrict__ ei, int E,
                               int* __restrict__ deg,
                               int* __restrict__ ticket) {
    int i = blockIdx.x * blockDim.x + threadIdx.x;
    if (i == 0) *ticket = 0;
    if (i < n8) {
        float4 a = src[i * 2];
        float4 b = src[i * 2 + 1];
        __half2 h0 = __floats2half2_rn(a.x, a.y);
        __half2 h1 = __floats2half2_rn(a.z, a.w);
        __half2 h2 = __floats2half2_rn(b.x, b.y);
        __half2 h3 = __floats2half2_rn(b.z, b.w);
        uint4 o;
        o.x = *(unsigned*)&h0;
        o.y = *(unsigned*)&h1;
        o.z = *(unsigned*)&h2;
        o.w = *(unsigned*)&h3;
        dst[i] = o;
    }
    if (i < E) atomicAdd(&deg[ei[(size_t)E + i]], 1);
}

// Fused scan: per-block scan writes local-exclusive into rowstart AND cursor;
// last block to finish scans the 98 block sums into blockoff.
__global__ void scan12_kernel(const int* __restrict__ deg,
                              int* __restrict__ rowstart,
                              int* __restrict__ cursor,
                              int* __restrict__ blocksum,
                              int* __restrict__ blockoff,
                              int* __restrict__ ticket, int n, int nb) {
    __shared__ int s[1024];
    __shared__ int isLast;
    int tid = threadIdx.x;
    int i = blockIdx.x * 1024 + tid;
    int v = (i < n) ? deg[i] : 0;
    s[tid] = v;
    __syncthreads();
#pragma unroll
    for (int off = 1; off < 1024; off <<= 1) {
        int t = (tid >= off) ? s[tid - off] : 0;
        __syncthreads();
        s[tid] += t;
        __syncthreads();
    }
    if (i < n) {
        int le = s[tid] - v;          // local exclusive
        rowstart[i] = le;
        cursor[i] = le;
    }
    if (tid == 1023) {
        blocksum[blockIdx.x] = s[tid];
        __threadfence();
    }
    __syncthreads();
    if (tid == 0) {
        int old = atomicAdd(ticket, 1);
        isLast = (old == nb - 1);
    }
    __syncthreads();
    if (isLast) {
        __threadfence();
        __shared__ int s2[128];
        int b = (tid < nb) ? ((volatile int*)blocksum)[tid] : 0;
        if (tid < 128) s2[tid] = b;
        __syncthreads();
#pragma unroll
        for (int off = 1; off < 128; off <<= 1) {
            int t = (tid < 128 && tid >= off) ? s2[tid - off] : 0;
            __syncthreads();
            if (tid < 128) s2[tid] += t;
            __syncthreads();
        }
        if (tid < nb) blockoff[tid] = s2[tid] - b;   // exclusive
    }
}

// CSR fill: global position = blockoff[dst>>10] + local cursor bump.
__global__ void fill_kernel(const int* __restrict__ ei, int E,
                            int* __restrict__ cursor,
                            const int* __restrict__ blockoff,
                            int* __restrict__ edge_src) {
    int e = blockIdx.x * blockDim.x + threadIdx.x;
    if (e < E) {
        int src = ei[e];
        int dst = ei[(size_t)E + e];
        int pos = blockoff[dst >> 10] + atomicAdd(&cursor[dst], 1);
        edge_src[pos] = src;
    }
}

// ---------------------------------------------------------------------------
// gather (fp16 payload, fp32 accumulate, fp16 output): LANES lanes per node.
template<int LANES>
__global__ void gather_to16_kernel(const uint4* __restrict__ feat16,
                                   const int* __restrict__ rowstart,
                                   const int* __restrict__ blockoff,
                                   const int* __restrict__ deg,
                                   const int* __restrict__ edge_src,
                                   uint4* __restrict__ dst16, int N) {
    long long gid = (long long)blockIdx.x * blockDim.x + threadIdx.x;
    int n = (int)(gid / LANES);
    if (n >= N) return;
    int lane = (int)(gid % LANES);
    int d = deg[n];
    int start = blockoff[n >> 10] + rowstart[n];
    float acc[8] = {0.f, 0.f, 0.f, 0.f, 0.f, 0.f, 0.f, 0.f};
    auto accum = [&](uint4 u) {
        float2 f0 = __half22float2(*(__half2*)&u.x);
        float2 f1 = __half22float2(*(__half2*)&u.y);
        float2 f2 = __half22float2(*(__half2*)&u.z);
        float2 f3 = __half22float2(*(__half2*)&u.w);
        acc[0] += f0.x; acc[1] += f0.y; acc[2] += f1.x; acc[3] += f1.y;
        acc[4] += f2.x; acc[5] += f2.y; acc[6] += f3.x; acc[7] += f3.y;
    };
    int j = 0;
    for (; j + 3 < d; j += 4) {
        int s0 = edge_src[start + j];
        int s1 = edge_src[start + j + 1];
        int s2 = edge_src[start + j + 2];
        int s3 = edge_src[start + j + 3];
        uint4 u0 = feat16[(size_t)s0 * LANES + lane];
        uint4 u1 = feat16[(size_t)s1 * LANES + lane];
        uint4 u2 = feat16[(size_t)s2 * LANES + lane];
        uint4 u3 = feat16[(size_t)s3 * LANES + lane];
        accum(u0); accum(u1); accum(u2); accum(u3);
    }
    for (; j < d; ++j)
        accum(feat16[(size_t)edge_src[start + j] * LANES + lane]);
    float inv = 1.0f / (float)max(d, 1);
    __half2 h0 = __floats2half2_rn(acc[0] * inv, acc[1] * inv);
    __half2 h1 = __floats2half2_rn(acc[2] * inv, acc[3] * inv);
    __half2 h2 = __floats2half2_rn(acc[4] * inv, acc[5] * inv);
    __half2 h3 = __floats2half2_rn(acc[6] * inv, acc[7] * inv);
    uint4 o;
    o.x = *(unsigned*)&h0; o.y = *(unsigned*)&h1;
    o.z = *(unsigned*)&h2; o.w = *(unsigned*)&h3;
    dst16[(size_t)n * LANES + lane] = o;
}

// gather (fp16 payload) accumulating into fp32 out
template<int LANES>
__global__ void gather_add32_kernel(const uint4* __restrict__ feat16,
                                    const int* __restrict__ rowstart,
                                    const int* __restrict__ blockoff,
                                    const int* __restrict__ deg,
                                    const int* __restrict__ edge_src,
                                    float* __restrict__ dstbuf, int N) {
    long long gid = (long long)blockIdx.x * blockDim.x + threadIdx.x;
    int n = (int)(gid / LANES);
    if (n >= N) return;
    int lane = (int)(gid % LANES);
    int d = deg[n];
    int start = blockoff[n >> 10] + rowstart[n];
    float acc[8] = {0.f, 0.f, 0.f, 0.f, 0.f, 0.f, 0.f, 0.f};
    auto accum = [&](uint4 u) {
        float2 f0 = __half22float2(*(__half2*)&u.x);
        float2 f1 = __half22float2(*(__half2*)&u.y);
        float2 f2 = __half22float2(*(__half2*)&u.z);
        float2 f3 = __half22float2(*(__half2*)&u.w);
        acc[0] += f0.x; acc[1] += f0.y; acc[2] += f1.x; acc[3] += f1.y;
        acc[4] += f2.x; acc[5] += f2.y; acc[6] += f3.x; acc[7] += f3.y;
    };
    int j = 0;
    for (; j + 3 < d; j += 4) {
        int s0 = edge_src[start + j];
        int s1 = edge_src[start + j + 1];
        int s2 = edge_src[start + j + 2];
        int s3 = edge_src[start + j + 3];
        uint4 u0 = feat16[(size_t)s0 * LANES + lane];
        uint4 u1 = feat16[(size_t)s1 * LANES + lane];
        uint4 u2 = feat16[(size_t)s2 * LANES + lane];
        uint4 u3 = feat16[(size_t)s3 * LANES + lane];
        accum(u0); accum(u1); accum(u2); accum(u3);
    }
    for (; j < d; ++j)
        accum(feat16[(size_t)edge_src[start + j] * LANES + lane]);
    float inv = 1.0f / (float)max(d, 1);
    float* p = dstbuf + (size_t)n * (LANES * 8) + lane * 8;
    float4 o0 = *(float4*)p, o1 = *(float4*)(p + 4);
    o0.x += acc[0] * inv; o0.y += acc[1] * inv;
    o0.z += acc[2] * inv; o0.w += acc[3] * inv;
    o1.x += acc[4] * inv; o1.y += acc[5] * inv;
    o1.z += acc[6] * inv; o1.w += acc[7] * inv;
    *(float4*)p = o0; *(float4*)(p + 4) = o1;
}

// ---------------------------------------------------------------------------
// fp16 tensor-core GEMM (m16n8k16, fp32 accumulate).
// Block 128x128, 8 warps (4M x 2N), warp tile 32x64, BK=32 halves.
// Smem stride 40 halves: fragment half2 load bank = (20g+t) mod 32 — conflict-free.
#define ASTRH 40

__device__ __forceinline__ void mma16n8k16(float* c, const unsigned* a,
                                           const unsigned* b) {
    asm volatile(
        "mma.sync.aligned.m16n8k16.row.col.f32.f16.f16.f32 "
        "{%0,%1,%2,%3}, {%4,%5,%6,%7}, {%8,%9}, {%0,%1,%2,%3};"
        : "+f"(c[0]), "+f"(c[1]), "+f"(c[2]), "+f"(c[3])
        : "r"(a[0]), "r"(a[1]), "r"(a[2]), "r"(a[3]), "r"(b[0]), "r"(b[1]));
}

__device__ __forceinline__ void mma_tile16(const __half* As, const __half* Ws,
                                           int wm, int wn, int g, int t,
                                           float c[2][8][4]) {
#pragma unroll
    for (int kc = 0; kc < 2; ++kc) {
        unsigned afr[2][4];
#pragma unroll
        for (int m = 0; m < 2; m++) {
            int r0 = wm * 32 + m * 16 + g;
            afr[m][0] = *(const unsigned*)&As[r0 * ASTRH + kc * 16 + 2 * t];
            afr[m][1] = *(const unsigned*)&As[(r0 + 8) * ASTRH + kc * 16 + 2 * t];
            afr[m][2] = *(const unsigned*)&As[r0 * ASTRH + kc * 16 + 8 + 2 * t];
            afr[m][3] = *(const unsigned*)&As[(r0 + 8) * ASTRH + kc * 16 + 8 + 2 * t];
        }
#pragma unroll
        for (int nt = 0; nt < 8; nt++) {
            int nrow = wn * 64 + nt * 8 + g;
            unsigned bfr[2] = {
                *(const unsigned*)&Ws[nrow * ASTRH + kc * 16 + 2 * t],
                *(const unsigned*)&Ws[nrow * ASTRH + kc * 16 + 8 + 2 * t]};
            mma16n8k16(c[0][nt], afr[0], bfr);
            mma16n8k16(c[1][nt], afr[1], bfr);
        }
    }
}

// GEMM1: h16 = relu(bn( [agg16 | x16] @ [W1l;W1r]^T + b1l )), K=256
__global__ __launch_bounds__(256)
void gemm1_f16(const __half* __restrict__ agg16,
               const __half* __restrict__ x16,
               const float* __restrict__ Wl,
               const float* __restrict__ Wr,
               const float* __restrict__ bias,
               const float* __restrict__ gamma,
               const float* __restrict__ beta,
               const float* __restrict__ mean,
               const float* __restrict__ var,
               __half* __restrict__ h16, int N) {
    __shared__ __half As[128 * ASTRH];
    __shared__ __half Ws[128 * ASTRH];
    const int tid = threadIdx.x;
    const int lane = tid & 31, warp = tid >> 5;
    const int wm = warp & 3, wn = warp >> 2;
    const int g = lane >> 2, t = lane & 3;
    const int blockRow = blockIdx.x * 128;
    const int arow = tid >> 2, aq = tid & 3;
    const int wrow = tid >> 3, wq = tid & 7;

    float c[2][8][4];
#pragma unroll
    for (int m = 0; m < 2; m++)
#pragma unroll
        for (int nt = 0; nt < 8; nt++)
#pragma unroll
            for (int q = 0; q < 4; q++) c[m][nt][q] = 0.f;

    uint4 va[2];
    float4 vw[4];
    auto loadRegs = [&](int kt) {
        const __half* Asrc = (kt < 4) ? agg16 : x16;
        const float* Wsrc = (kt < 4) ? Wl : Wr;
        const int kloc = (kt & 3) * 32;
#pragma unroll
        for (int p = 0; p < 2; ++p) {
            int row = arow + p * 64;
            int n = blockRow + row;
            va[p] = make_uint4(0, 0, 0, 0);
            if (n < N)
                va[p] = *(const uint4*)(Asrc + (size_t)n * 128 + kloc + aq * 8);
        }
#pragma unroll
        for (int p = 0; p < 4; ++p) {
            int row = wrow + p * 32;
            vw[p] = *(const float4*)(Wsrc + (size_t)row * 128 + kloc + wq * 4);
        }
    };
    auto storeSmem = [&]() {
#pragma unroll
        for (int p = 0; p < 2; ++p) {
            int row = arow + p * 64;
            *(uint4*)&As[row * ASTRH + aq * 8] = va[p];
        }
#pragma unroll
        for (int p = 0; p < 4; ++p) {
            int row = wrow + p * 32;
            __half2 lo = __floats2half2_rn(vw[p].x, vw[p].y);
            __half2 hi = __floats2half2_rn(vw[p].z, vw[p].w);
            uint2 u = make_uint2(*(unsigned*)&lo, *(unsigned*)&hi);
            *(uint2*)&Ws[row * ASTRH + wq * 4] = u;
        }
    };

    loadRegs(0);
    storeSmem();
    __syncthreads();
    for (int kt = 0; kt < 8; ++kt) {
        if (kt < 7) loadRegs(kt + 1);
        mma_tile16(As, Ws, wm, wn, g, t, c);
        __syncthreads();
        if (kt < 7) {
            storeSmem();
            __syncthreads();
        }
    }

#pragma unroll
    for (int nt = 0; nt < 8; nt++) {
        int col0 = wn * 64 + nt * 8 + 2 * t;
        float s0 = gamma[col0] * rsqrtf(var[col0] + BN_EPS);
        float s1 = gamma[col0 + 1] * rsqrtf(var[col0 + 1] + BN_EPS);
        float t0 = beta[col0] - mean[col0] * s0 + bias[col0] * s0;
        float t1 = beta[col0 + 1] - mean[col0 + 1] * s1 + bias[col0 + 1] * s1;
#pragma unroll
        for (int m = 0; m < 2; m++) {
            int r = blockRow + wm * 32 + m * 16 + g;
            if (r < N) {
                __half2 v = __floats2half2_rn(fmaxf(c[m][nt][0] * s0 + t0, 0.f),
                                              fmaxf(c[m][nt][1] * s1 + t1, 0.f));
                *(__half2*)(h16 + (size_t)r * 128 + col0) = v;
            }
            int r2 = r + 8;
            if (r2 < N) {
                __half2 v = __floats2half2_rn(fmaxf(c[m][nt][2] * s0 + t0, 0.f),
                                              fmaxf(c[m][nt][3] * s1 + t1, 0.f));
                *(__half2*)(h16 + (size_t)r2 * 128 + col0) = v;
            }
        }
    }
}

// GEMM2: K=128; wn==0 -> p16 = fp16(h@W2l^T); wn==1 -> out = h@W2r^T + b2l
__global__ __launch_bounds__(256)
void gemm2_f16(const __half* __restrict__ h16,
               const float* __restrict__ W2l,
               const float* __restrict__ W2r,
               const float* __restrict__ b2l,
               __half* __restrict__ p16,
               float* __restrict__ out, int N) {
    __shared__ __half As[128 * ASTRH];
    __shared__ __half Ws[128 * ASTRH];
    const int tid = threadIdx.x;
    const int lane = tid & 31, warp = tid >> 5;
    const int wm = warp & 3, wn = warp >> 2;
    const int g = lane >> 2, t = lane & 3;
    const int blockRow = blockIdx.x * 128;
    const int arow = tid >> 2, aq = tid & 3;
    const int wrow = tid >> 3, wq = tid & 7;

    float c[2][8][4];
#pragma unroll
    for (int m = 0; m < 2; m++)
#pragma unroll
        for (int nt = 0; nt < 8; nt++)
#pragma unroll
            for (int q = 0; q < 4; q++) c[m][nt][q] = 0.f;

    uint4 va[2];
    float4 vw[4];
    auto loadRegs = [&](int kt) {
        const int kloc = kt * 32;
#pragma unroll
        for (int p = 0; p < 2; ++p) {
            int row = arow + p * 64;
            int n = blockRow + row;
            va[p] = make_uint4(0, 0, 0, 0);
            if (n < N)
                va[p] = *(const uint4*)(h16 + (size_t)n * 128 + kloc + aq * 8);
        }
#pragma unroll
        for (int p = 0; p < 4; ++p) {
            int row = wrow + p * 32;
            const float* Wsrc = (row < 64) ? (W2l + (size_t)row * 128)
                                           : (W2r + (size_t)(row - 64) * 128);
            vw[p] = *(const float4*)(Wsrc + kloc + wq * 4);
        }
    };
    auto storeSmem = [&]() {
#pragma unroll
        for (int p = 0; p < 2; ++p) {
            int row = arow + p * 64;
            *(uint4*)&As[row * ASTRH + aq * 8] = va[p];
        }
#pragma unroll
        for (int p = 0; p < 4; ++p) {
            int row = wrow + p * 32;
            __half2 lo = __floats2half2_rn(vw[p].x, vw[p].y);
            __half2 hi = __floats2half2_rn(vw[p].z, vw[p].w);
            uint2 u = make_uint2(*(unsigned*)&lo, *(unsigned*)&hi);
            *(uint2*)&Ws[row * ASTRH + wq * 4] = u;
        }
    };

    loadRegs(0);
    storeSmem();
    __syncthreads();
    for (int kt = 0; kt < 4; ++kt) {
        if (kt < 3) loadRegs(kt + 1);
        mma_tile16(As, Ws, wm, wn, g, t, c);
        __syncthreads();
        if (kt < 3) {
            storeSmem();
            __syncthreads();
        }
    }

    if (wn == 0) {   // p16, cols 0..63, no bias
#pragma unroll
        for (int nt = 0; nt < 8; nt++) {
            int col0 = nt * 8 + 2 * t;
#pragma unroll
            for (int m = 0; m < 2; m++) {
                int r = blockRow + wm * 32 + m * 16 + g;
                if (r < N) {
                    __half2 v = __floats2half2_rn(c[m][nt][0], c[m][nt][1]);
                    *(__half2*)(p16 + (size_t)r * 64 + col0) = v;
                }
                int r2 = r + 8;
                if (r2 < N) {
                    __half2 v = __floats2half2_rn(c[m][nt][2], c[m][nt][3]);
                    *(__half2*)(p16 + (size_t)r2 * 64 + col0) = v;
                }
            }
        }
    } else {         // out, + bias
#pragma unroll
        for (int nt = 0; nt < 8; nt++) {
            int col0 = nt * 8 + 2 * t;
            float b0 = b2l[col0], b1 = b2l[col0 + 1];
#pragma unroll
            for (int m = 0; m < 2; m++) {
                int r = blockRow + wm * 32 + m * 16 + g;
                if (r < N)
                    *(float2*)(out + (size_t)r * 64 + col0) =
                        make_float2(c[m][nt][0] + b0, c[m][nt][1] + b1);
                int r2 = r + 8;
                if (r2 < N)
                    *(float2*)(out + (size_t)r2 * 64 + col0) =
                        make_float2(c[m][nt][2] + b0, c[m][nt][3] + b1);
            }
        }
    }
}

// ---------------------------------------------------------------------------
extern "C" void kernel_launch(void* const* d_in, const int* in_sizes, int n_in,
                              void* d_out, int out_size) {
    const float* x        = (const float*)d_in[0];
    const int* ei         = (const int*)d_in[1];   // int32 (JAX x64 disabled)
    const float* W1l      = (const float*)d_in[2];
    const float* b1l      = (const float*)d_in[3];
    const float* W1r      = (const float*)d_in[4];
    const float* bn_gamma = (const float*)d_in[5];
    const float* bn_beta  = (const float*)d_in[6];
    const float* bn_mean  = (const float*)d_in[7];
    const float* bn_var   = (const float*)d_in[8];
    const float* W2l      = (const float*)d_in[9];
    const float* b2l      = (const float*)d_in[10];
    const float* W2r      = (const float*)d_in[11];
    float* out            = (float*)d_out;

    const int N = N_NODES_C;
    const int E = in_sizes[1] / 2;

    __half *agg16, *h16, *x16, *p16;
    int *deg, *rowstart, *cursor, *blocksum, *blockoff, *ticket, *edge_src;
    cudaGetSymbolAddress((void**)&agg16, g_agg16);
    cudaGetSymbolAddress((void**)&h16, g_h16);
    cudaGetSymbolAddress((void**)&x16, g_x16);
    cudaGetSymbolAddress((void**)&p16, g_p16);
    cudaGetSymbolAddress((void**)&deg, g_deg);
    cudaGetSymbolAddress((void**)&rowstart, g_rowstart);
    cudaGetSymbolAddress((void**)&cursor, g_cursor);
    cudaGetSymbolAddress((void**)&blocksum, g_blocksum);
    cudaGetSymbolAddress((void**)&blockoff, g_blockoff);
    cudaGetSymbolAddress((void**)&ticket, g_ticket);
    cudaGetSymbolAddress((void**)&edge_src, g_edge_src);

    const int nb = (N + 1023) / 1024;   // 98 scan blocks
    const int n8 = N * 128 / 8;         // 1.6M cvt threads

    // 1) zero deg (graph-capturable)
    cudaMemsetAsync(deg, 0, N * sizeof(int));
    // 2) fused cvt(x->fp16) + degree histogram + ticket reset
    {
        int work = (n8 > E) ? n8 : E;
        cvthist_kernel<<<(work + 255) / 256, 256>>>(
            (const float4*)x, (uint4*)x16, n8, ei, E, deg, ticket);
    }
    // 3) fused block scan + blocksum scan (writes rowstart+cursor local-excl)
    scan12_kernel<<<nb, 1024>>>(deg, rowstart, cursor, blocksum, blockoff,
                                ticket, N, nb);
    // 4) CSR fill (applies blockoff inline)
    fill_kernel<<<(E + 255) / 256, 256>>>(ei, E, cursor, blockoff, edge_src);

    // 5) Layer 1 gather: agg16 = mean-gather(x16)
    {
        long long threads = (long long)N * 16;
        gather_to16_kernel<16><<<(int)((threads + 255) / 256), 256>>>(
            (const uint4*)x16, rowstart, blockoff, deg, edge_src,
            (uint4*)agg16, N);
    }
    // 6) GEMM1 -> h16
    gemm1_f16<<<(N + 127) / 128, 256>>>(
        agg16, x16, W1l, W1r, b1l, bn_gamma, bn_beta, bn_mean, bn_var, h16, N);
    // 7) GEMM2 -> p16 + out
    gemm2_f16<<<(N + 127) / 128, 256>>>(h16, W2l, W2r, b2l, p16, out, N);
    // 8) Layer 2 gather: out += mean-gather(p16)
    {
        long long threads = (long long)N * 8;
        gather_add32_kernel<8><<<(int)((threads + 255) / 256), 256>>>(
            (const uint4*)p16, rowstart, blockoff, deg, edge_src, out, N);
    }
}

// round 16
// speedup vs baseline: 6.6624x; 1.0013x over previous
#include <cuda_runtime.h>
#include <cuda_fp16.h>

#define N_NODES_C 100000
#define E_MAX_C   1600000
#define BN_EPS 1e-5f

// Scratch (device globals — no allocation allowed)
__device__ __half g_agg16[(size_t)N_NODES_C * 128];
__device__ __half g_h16[(size_t)N_NODES_C * 128];
__device__ __half g_x16[(size_t)N_NODES_C * 128];
__device__ __half g_p16[(size_t)N_NODES_C * 64];
__device__ int    g_deg[N_NODES_C];
__device__ int    g_rowstart[N_NODES_C];   // local-exclusive (within scan block)
__device__ int    g_cursor[N_NODES_C];     // local-exclusive copy for fill
__device__ int    g_blocksum[128];
__device__ int    g_blockoff[128];
__device__ int    g_ticket[1];
__device__ int    g_edge_src[E_MAX_C];

// ---------------------------------------------------------------------------
// Fused: x->fp16 conversion + degree histogram (+ticket reset).
// deg must be zeroed beforehand (memsetAsync).
__global__ void cvthist_kernel(const float4* __restrict__ src,
                               uint4* __restrict__ dst, int n8,
                               const int* __restrict__ ei, int E,
                               int* __restrict__ deg,
                               int* __restrict__ ticket) {
    int i = blockIdx.x * blockDim.x + threadIdx.x;
    if (i == 0) *ticket = 0;
    if (i < n8) {
        float4 a = src[i * 2];
        float4 b = src[i * 2 + 1];
        __half2 h0 = __floats2half2_rn(a.x, a.y);
        __half2 h1 = __floats2half2_rn(a.z, a.w);
        __half2 h2 = __floats2half2_rn(b.x, b.y);
        __half2 h3 = __floats2half2_rn(b.z, b.w);
        uint4 o;
        o.x = *(unsigned*)&h0;
        o.y = *(unsigned*)&h1;
        o.z = *(unsigned*)&h2;
        o.w = *(unsigned*)&h3;
        dst[i] = o;
    }
    if (i < E) atomicAdd(&deg[ei[(size_t)E + i]], 1);
}

// Fused scan: per-block scan writes local-exclusive into rowstart AND cursor;
// last block to finish scans the 98 block sums into blockoff.
__global__ void scan12_kernel(const int* __restrict__ deg,
                              int* __restrict__ rowstart,
                              int* __restrict__ cursor,
                              int* __restrict__ blocksum,
                              int* __restrict__ blockoff,
                              int* __restrict__ ticket, int n, int nb) {
    __shared__ int s[1024];
    __shared__ int isLast;
    int tid = threadIdx.x;
    int i = blockIdx.x * 1024 + tid;
    int v = (i < n) ? deg[i] : 0;
    s[tid] = v;
    __syncthreads();
#pragma unroll
    for (int off = 1; off < 1024; off <<= 1) {
        int t = (tid >= off) ? s[tid - off] : 0;
        __syncthreads();
        s[tid] += t;
        __syncthreads();
    }
    if (i < n) {
        int le = s[tid] - v;          // local exclusive
        rowstart[i] = le;
        cursor[i] = le;
    }
    if (tid == 1023) {
        blocksum[blockIdx.x] = s[tid];
        __threadfence();
    }
    __syncthreads();
    if (tid == 0) {
        int old = atomicAdd(ticket, 1);
        isLast = (old == nb - 1);
    }
    __syncthreads();
    if (isLast) {
        __threadfence();
        __shared__ int s2[128];
        int b = (tid < nb) ? ((volatile int*)blocksum)[tid] : 0;
        if (tid < 128) s2[tid] = b;
        __syncthreads();
#pragma unroll
        for (int off = 1; off < 128; off <<= 1) {
            int t = (tid < 128 && tid >= off) ? s2[tid - off] : 0;
            __syncthreads();
            if (tid < 128) s2[tid] += t;
            __syncthreads();
        }
        if (tid < nb) blockoff[tid] = s2[tid] - b;   // exclusive
    }
}

// CSR fill: global position = blockoff[dst>>10] + local cursor bump.
__global__ void fill_kernel(const int* __restrict__ ei, int E,
                            int* __restrict__ cursor,
                            const int* __restrict__ blockoff,
                            int* __restrict__ edge_src) {
    int e = blockIdx.x * blockDim.x + threadIdx.x;
    if (e < E) {
        int src = ei[e];
        int dst = ei[(size_t)E + e];
        int pos = blockoff[dst >> 10] + atomicAdd(&cursor[dst], 1);
        edge_src[pos] = src;
    }
}

// ---------------------------------------------------------------------------
// Pairwise fp16 add of two uint4 payloads (8 halves each): 4 HADD2.
__device__ __forceinline__ uint4 hadd2x4(uint4 a, uint4 b) {
    __half2 r0 = __hadd2(*(__half2*)&a.x, *(__half2*)&b.x);
    __half2 r1 = __hadd2(*(__half2*)&a.y, *(__half2*)&b.y);
    __half2 r2 = __hadd2(*(__half2*)&a.z, *(__half2*)&b.z);
    __half2 r3 = __hadd2(*(__half2*)&a.w, *(__half2*)&b.w);
    uint4 o;
    o.x = *(unsigned*)&r0; o.y = *(unsigned*)&r1;
    o.z = *(unsigned*)&r2; o.w = *(unsigned*)&r3;
    return o;
}

// gather core: LANES lanes per node, fp16 payload, pairwise fp16 pre-add,
// fp32 accumulate. Unroll 8 (MLP 8).
template<int LANES>
__device__ __forceinline__ void gather_core(const uint4* __restrict__ feat16,
                                            const int* __restrict__ rowstart,
                                            const int* __restrict__ blockoff,
                                            const int* __restrict__ deg,
                                            const int* __restrict__ edge_src,
                                            int n, int lane, int& dout,
                                            float acc[8]) {
    int d = deg[n];
    int start = blockoff[n >> 10] + rowstart[n];
    dout = d;
#pragma unroll
    for (int q = 0; q < 8; q++) acc[q] = 0.f;

    auto accum = [&](uint4 u) {
        float2 f0 = __half22float2(*(__half2*)&u.x);
        float2 f1 = __half22float2(*(__half2*)&u.y);
        float2 f2 = __half22float2(*(__half2*)&u.z);
        float2 f3 = __half22float2(*(__half2*)&u.w);
        acc[0] += f0.x; acc[1] += f0.y; acc[2] += f1.x; acc[3] += f1.y;
        acc[4] += f2.x; acc[5] += f2.y; acc[6] += f3.x; acc[7] += f3.y;
    };

    int j = 0;
    for (; j + 7 < d; j += 8) {
        int s0 = edge_src[start + j];
        int s1 = edge_src[start + j + 1];
        int s2 = edge_src[start + j + 2];
        int s3 = edge_src[start + j + 3];
        int s4 = edge_src[start + j + 4];
        int s5 = edge_src[start + j + 5];
        int s6 = edge_src[start + j + 6];
        int s7 = edge_src[start + j + 7];
        uint4 u0 = feat16[(size_t)s0 * LANES + lane];
        uint4 u1 = feat16[(size_t)s1 * LANES + lane];
        uint4 u2 = feat16[(size_t)s2 * LANES + lane];
        uint4 u3 = feat16[(size_t)s3 * LANES + lane];
        uint4 u4 = feat16[(size_t)s4 * LANES + lane];
        uint4 u5 = feat16[(size_t)s5 * LANES + lane];
        uint4 u6 = feat16[(size_t)s6 * LANES + lane];
        uint4 u7 = feat16[(size_t)s7 * LANES + lane];
        accum(hadd2x4(u0, u1));
        accum(hadd2x4(u2, u3));
        accum(hadd2x4(u4, u5));
        accum(hadd2x4(u6, u7));
    }
    for (; j + 1 < d; j += 2) {
        int s0 = edge_src[start + j];
        int s1 = edge_src[start + j + 1];
        uint4 u0 = feat16[(size_t)s0 * LANES + lane];
        uint4 u1 = feat16[(size_t)s1 * LANES + lane];
        accum(hadd2x4(u0, u1));
    }
    if (j < d)
        accum(feat16[(size_t)edge_src[start + j] * LANES + lane]);
}

// gather (fp16 payload) -> fp16 output
template<int LANES>
__global__ void gather_to16_kernel(const uint4* __restrict__ feat16,
                                   const int* __restrict__ rowstart,
                                   const int* __restrict__ blockoff,
                                   const int* __restrict__ deg,
                                   const int* __restrict__ edge_src,
                                   uint4* __restrict__ dst16, int N) {
    long long gid = (long long)blockIdx.x * blockDim.x + threadIdx.x;
    int n = (int)(gid / LANES);
    if (n >= N) return;
    int lane = (int)(gid % LANES);
    int d;
    float acc[8];
    gather_core<LANES>(feat16, rowstart, blockoff, deg, edge_src, n, lane, d, acc);
    float inv = 1.0f / (float)max(d, 1);
    __half2 h0 = __floats2half2_rn(acc[0] * inv, acc[1] * inv);
    __half2 h1 = __floats2half2_rn(acc[2] * inv, acc[3] * inv);
    __half2 h2 = __floats2half2_rn(acc[4] * inv, acc[5] * inv);
    __half2 h3 = __floats2half2_rn(acc[6] * inv, acc[7] * inv);
    uint4 o;
    o.x = *(unsigned*)&h0; o.y = *(unsigned*)&h1;
    o.z = *(unsigned*)&h2; o.w = *(unsigned*)&h3;
    dst16[(size_t)n * LANES + lane] = o;
}

// gather (fp16 payload) accumulating into fp32 out
template<int LANES>
__global__ void gather_add32_kernel(const uint4* __restrict__ feat16,
                                    const int* __restrict__ rowstart,
                                    const int* __restrict__ blockoff,
                                    const int* __restrict__ deg,
                                    const int* __restrict__ edge_src,
                                    float* __restrict__ dstbuf, int N) {
    long long gid = (long long)blockIdx.x * blockDim.x + threadIdx.x;
    int n = (int)(gid / LANES);
    if (n >= N) return;
    int lane = (int)(gid % LANES);
    int d;
    float acc[8];
    gather_core<LANES>(feat16, rowstart, blockoff, deg, edge_src, n, lane, d, acc);
    float inv = 1.0f / (float)max(d, 1);
    float* p = dstbuf + (size_t)n * (LANES * 8) + lane * 8;
    float4 o0 = *(float4*)p, o1 = *(float4*)(p + 4);
    o0.x += acc[0] * inv; o0.y += acc[1] * inv;
    o0.z += acc[2] * inv; o0.w += acc[3] * inv;
    o1.x += acc[4] * inv; o1.y += acc[5] * inv;
    o1.z += acc[6] * inv; o1.w += acc[7] * inv;
    *(float4*)p = o0; *(float4*)(p + 4) = o1;
}

// ---------------------------------------------------------------------------
// fp16 tensor-core GEMM (m16n8k16, fp32 accumulate).
// Block 128x128, 8 warps (4M x 2N), warp tile 32x64, BK=32 halves.
// Smem stride 40 halves: fragment half2 load bank = (20g+t) mod 32 — conflict-free.
#define ASTRH 40

__device__ __forceinline__ void mma16n8k16(float* c, const unsigned* a,
                                           const unsigned* b) {
    asm volatile(
        "mma.sync.aligned.m16n8k16.row.col.f32.f16.f16.f32 "
        "{%0,%1,%2,%3}, {%4,%5,%6,%7}, {%8,%9}, {%0,%1,%2,%3};"
        : "+f"(c[0]), "+f"(c[1]), "+f"(c[2]), "+f"(c[3])
        : "r"(a[0]), "r"(a[1]), "r"(a[2]), "r"(a[3]), "r"(b[0]), "r"(b[1]));
}

__device__ __forceinline__ void mma_tile16(const __half* As, const __half* Ws,
                                           int wm, int wn, int g, int t,
                                           float c[2][8][4]) {
#pragma unroll
    for (int kc = 0; kc < 2; ++kc) {
        unsigned afr[2][4];
#pragma unroll
        for (int m = 0; m < 2; m++) {
            int r0 = wm * 32 + m * 16 + g;
            afr[m][0] = *(const unsigned*)&As[r0 * ASTRH + kc * 16 + 2 * t];
            afr[m][1] = *(const unsigned*)&As[(r0 + 8) * ASTRH + kc * 16 + 2 * t];
            afr[m][2] = *(const unsigned*)&As[r0 * ASTRH + kc * 16 + 8 + 2 * t];
            afr[m][3] = *(const unsigned*)&As[(r0 + 8) * ASTRH + kc * 16 + 8 + 2 * t];
        }
#pragma unroll
        for (int nt = 0; nt < 8; nt++) {
            int nrow = wn * 64 + nt * 8 + g;
            unsigned bfr[2] = {
                *(const unsigned*)&Ws[nrow * ASTRH + kc * 16 + 2 * t],
                *(const unsigned*)&Ws[nrow * ASTRH + kc * 16 + 8 + 2 * t]};
            mma16n8k16(c[0][nt], afr[0], bfr);
            mma16n8k16(c[1][nt], afr[1], bfr);
        }
    }
}

// GEMM1: h16 = relu(bn( [agg16 | x16] @ [W1l;W1r]^T + b1l )), K=256
__global__ __launch_bounds__(256)
void gemm1_f16(const __half* __restrict__ agg16,
               const __half* __restrict__ x16,
               const float* __restrict__ Wl,
               const float* __restrict__ Wr,
               const float* __restrict__ bias,
               const float* __restrict__ gamma,
               const float* __restrict__ beta,
               const float* __restrict__ mean,
               const float* __restrict__ var,
               __half* __restrict__ h16, int N) {
    __shared__ __half As[128 * ASTRH];
    __shared__ __half Ws[128 * ASTRH];
    const int tid = threadIdx.x;
    const int lane = tid & 31, warp = tid >> 5;
    const int wm = warp & 3, wn = warp >> 2;
    const int g = lane >> 2, t = lane & 3;
    const int blockRow = blockIdx.x * 128;
    const int arow = tid >> 2, aq = tid & 3;
    const int wrow = tid >> 3, wq = tid & 7;

    float c[2][8][4];
#pragma unroll
    for (int m = 0; m < 2; m++)
#pragma unroll
        for (int nt = 0; nt < 8; nt++)
#pragma unroll
            for (int q = 0; q < 4; q++) c[m][nt][q] = 0.f;

    uint4 va[2];
    float4 vw[4];
    auto loadRegs = [&](int kt) {
        const __half* Asrc = (kt < 4) ? agg16 : x16;
        const float* Wsrc = (kt < 4) ? Wl : Wr;
        const int kloc = (kt & 3) * 32;
#pragma unroll
        for (int p = 0; p < 2; ++p) {
            int row = arow + p * 64;
            int n = blockRow + row;
            va[p] = make_uint4(0, 0, 0, 0);
            if (n < N)
                va[p] = *(const uint4*)(Asrc + (size_t)n * 128 + kloc + aq * 8);
        }
#pragma unroll
        for (int p = 0; p < 4; ++p) {
            int row = wrow + p * 32;
            vw[p] = *(const float4*)(Wsrc + (size_t)row * 128 + kloc + wq * 4);
        }
    };
    auto storeSmem = [&]() {
#pragma unroll
        for (int p = 0; p < 2; ++p) {
            int row = arow + p * 64;
            *(uint4*)&As[row * ASTRH + aq * 8] = va[p];
        }
#pragma unroll
        for (int p = 0; p < 4; ++p) {
            int row = wrow + p * 32;
            __half2 lo = __floats2half2_rn(vw[p].x, vw[p].y);
            __half2 hi = __floats2half2_rn(vw[p].z, vw[p].w);
            uint2 u = make_uint2(*(unsigned*)&lo, *(unsigned*)&hi);
            *(uint2*)&Ws[row * ASTRH + wq * 4] = u;
        }
    };

    loadRegs(0);
    storeSmem();
    __syncthreads();
    for (int kt = 0; kt < 8; ++kt) {
        if (kt < 7) loadRegs(kt + 1);
        mma_tile16(As, Ws, wm, wn, g, t, c);
        __syncthreads();
        if (kt < 7) {
            storeSmem();
            __syncthreads();
        }
    }

#pragma unroll
    for (int nt = 0; nt < 8; nt++) {
        int col0 = wn * 64 + nt * 8 + 2 * t;
        float s0 = gamma[col0] * rsqrtf(var[col0] + BN_EPS);
        float s1 = gamma[col0 + 1] * rsqrtf(var[col0 + 1] + BN_EPS);
        float t0 = beta[col0] - mean[col0] * s0 + bias[col0] * s0;
        float t1 = beta[col0 + 1] - mean[col0 + 1] * s1 + bias[col0 + 1] * s1;
#pragma unroll
        for (int m = 0; m < 2; m++) {
            int r = blockRow + wm * 32 + m * 16 + g;
            if (r < N) {
                __half2 v = __floats2half2_rn(fmaxf(c[m][nt][0] * s0 + t0, 0.f),
                                              fmaxf(c[m][nt][1] * s1 + t1, 0.f));
                *(__half2*)(h16 + (size_t)r * 128 + col0) = v;
            }
            int r2 = r + 8;
            if (r2 < N) {
                __half2 v = __floats2half2_rn(fmaxf(c[m][nt][2] * s0 + t0, 0.f),
                                              fmaxf(c[m][nt][3] * s1 + t1, 0.f));
                *(__half2*)(h16 + (size_t)r2 * 128 + col0) = v;
            }
        }
    }
}

// GEMM2: K=128; wn==0 -> p16 = fp16(h@W2l^T); wn==1 -> out = h@W2r^T + b2l
__global__ __launch_bounds__(256)
void gemm2_f16(const __half* __restrict__ h16,
               const float* __restrict__ W2l,
               const float* __restrict__ W2r,
               const float* __restrict__ b2l,
               __half* __restrict__ p16,
               float* __restrict__ out, int N) {
    __shared__ __half As[128 * ASTRH];
    __shared__ __half Ws[128 * ASTRH];
    const int tid = threadIdx.x;
    const int lane = tid & 31, warp = tid >> 5;
    const int wm = warp & 3, wn = warp >> 2;
    const int g = lane >> 2, t = lane & 3;
    const int blockRow = blockIdx.x * 128;
    const int arow = tid >> 2, aq = tid & 3;
    const int wrow = tid >> 3, wq = tid & 7;

    float c[2][8][4];
#pragma unroll
    for (int m = 0; m < 2; m++)
#pragma unroll
        for (int nt = 0; nt < 8; nt++)
#pragma unroll
            for (int q = 0; q < 4; q++) c[m][nt][q] = 0.f;

    uint4 va[2];
    float4 vw[4];
    auto loadRegs = [&](int kt) {
        const int kloc = kt * 32;
#pragma unroll
        for (int p = 0; p < 2; ++p) {
            int row = arow + p * 64;
            int n = blockRow + row;
            va[p] = make_uint4(0, 0, 0, 0);
            if (n < N)
                va[p] = *(const uint4*)(h16 + (size_t)n * 128 + kloc + aq * 8);
        }
#pragma unroll
        for (int p = 0; p < 4; ++p) {
            int row = wrow + p * 32;
            const float* Wsrc = (row < 64) ? (W2l + (size_t)row * 128)
                                           : (W2r + (size_t)(row - 64) * 128);
            vw[p] = *(const float4*)(Wsrc + kloc + wq * 4);
        }
    };
    auto storeSmem = [&]() {
#pragma unroll
        for (int p = 0; p < 2; ++p) {
            int row = arow + p * 64;
            *(uint4*)&As[row * ASTRH + aq * 8] = va[p];
        }
#pragma unroll
        for (int p = 0; p < 4; ++p) {
            int row = wrow + p * 32;
            __half2 lo = __floats2half2_rn(vw[p].x, vw[p].y);
            __half2 hi = __floats2half2_rn(vw[p].z, vw[p].w);
            uint2 u = make_uint2(*(unsigned*)&lo, *(unsigned*)&hi);
            *(uint2*)&Ws[row * ASTRH + wq * 4] = u;
        }
    };

    loadRegs(0);
    storeSmem();
    __syncthreads();
    for (int kt = 0; kt < 4; ++kt) {
        if (kt < 3) loadRegs(kt + 1);
        mma_tile16(As, Ws, wm, wn, g, t, c);
        __syncthreads();
        if (kt < 3) {
            storeSmem();
            __syncthreads();
        }
    }

    if (wn == 0) {   // p16, cols 0..63, no bias
#pragma unroll
        for (int nt = 0; nt < 8; nt++) {
            int col0 = nt * 8 + 2 * t;
#pragma unroll
            for (int m = 0; m < 2; m++) {
                int r = blockRow + wm * 32 + m * 16 + g;
                if (r < N) {
                    __half2 v = __floats2half2_rn(c[m][nt][0], c[m][nt][1]);
                    *(__half2*)(p16 + (size_t)r * 64 + col0) = v;
                }
                int r2 = r + 8;
                if (r2 < N) {
                    __half2 v = __floats2half2_rn(c[m][nt][2], c[m][nt][3]);
                    *(__half2*)(p16 + (size_t)r2 * 64 + col0) = v;
                }
            }
        }
    } else {         // out, + bias
#pragma unroll
        for (int nt = 0; nt < 8; nt++) {
            int col0 = nt * 8 + 2 * t;
            float b0 = b2l[col0], b1 = b2l[col0 + 1];
#pragma unroll
            for (int m = 0; m < 2; m++) {
                int r = blockRow + wm * 32 + m * 16 + g;
                if (r < N)
                    *(float2*)(out + (size_t)r * 64 + col0) =
                        make_float2(c[m][nt][0] + b0, c[m][nt][1] + b1);
                int r2 = r + 8;
                if (r2 < N)
                    *(float2*)(out + (size_t)r2 * 64 + col0) =
                        make_float2(c[m][nt][2] + b0, c[m][nt][3] + b1);
            }
        }
    }
}

// ---------------------------------------------------------------------------
extern "C" void kernel_launch(void* const* d_in, const int* in_sizes, int n_in,
                              void* d_out, int out_size) {
    const float* x        = (const float*)d_in[0];
    const int* ei         = (const int*)d_in[1];   // int32 (JAX x64 disabled)
    const float* W1l      = (const float*)d_in[2];
    const float* b1l      = (const float*)d_in[3];
    const float* W1r      = (const float*)d_in[4];
    const float* bn_gamma = (const float*)d_in[5];
    const float* bn_beta  = (const float*)d_in[6];
    const float* bn_mean  = (const float*)d_in[7];
    const float* bn_var   = (const float*)d_in[8];
    const float* W2l      = (const float*)d_in[9];
    const float* b2l      = (const float*)d_in[10];
    const float* W2r      = (const float*)d_in[11];
    float* out            = (float*)d_out;

    const int N = N_NODES_C;
    const int E = in_sizes[1] / 2;

    __half *agg16, *h16, *x16, *p16;
    int *deg, *rowstart, *cursor, *blocksum, *blockoff, *ticket, *edge_src;
    cudaGetSymbolAddress((void**)&agg16, g_agg16);
    cudaGetSymbolAddress((void**)&h16, g_h16);
    cudaGetSymbolAddress((void**)&x16, g_x16);
    cudaGetSymbolAddress((void**)&p16, g_p16);
    cudaGetSymbolAddress((void**)&deg, g_deg);
    cudaGetSymbolAddress((void**)&rowstart, g_rowstart);
    cudaGetSymbolAddress((void**)&cursor, g_cursor);
    cudaGetSymbolAddress((void**)&blocksum, g_blocksum);
    cudaGetSymbolAddress((void**)&blockoff, g_blockoff);
    cudaGetSymbolAddress((void**)&ticket, g_ticket);
    cudaGetSymbolAddress((void**)&edge_src, g_edge_src);

    const int nb = (N + 1023) / 1024;   // 98 scan blocks
    const int n8 = N * 128 / 8;         // 1.6M cvt threads

    // 1) zero deg (graph-capturable)
    cudaMemsetAsync(deg, 0, N * sizeof(int));
    // 2) fused cvt(x->fp16) + degree histogram + ticket reset
    {
        int work = (n8 > E) ? n8 : E;
        cvthist_kernel<<<(work + 255) / 256, 256>>>(
            (const float4*)x, (uint4*)x16, n8, ei, E, deg, ticket);
    }
    // 3) fused block scan + blocksum scan (writes rowstart+cursor local-excl)
    scan12_kernel<<<nb, 1024>>>(deg, rowstart, cursor, blocksum, blockoff,
                                ticket, N, nb);
    // 4) CSR fill (applies blockoff inline)
    fill_kernel<<<(E + 255) / 256, 256>>>(ei, E, cursor, blockoff, edge_src);

    // 5) Layer 1 gather: agg16 = mean-gather(x16)
    {
        long long threads = (long long)N * 16;
        gather_to16_kernel<16><<<(int)((threads + 255) / 256), 256>>>(
            (const uint4*)x16, rowstart, blockoff, deg, edge_src,
            (uint4*)agg16, N);
    }
    // 6) GEMM1 -> h16
    gemm1_f16<<<(N + 127) / 128, 256>>>(
        agg16, x16, W1l, W1r, b1l, bn_gamma, bn_beta, bn_mean, bn_var, h16, N);
    // 7) GEMM2 -> p16 + out
    gemm2_f16<<<(N + 127) / 128, 256>>>(h16, W2l, W2r, b2l, p16, out, N);
    // 8) Layer 2 gather: out += mean-gather(p16)
    {
        long long threads = (long long)N * 8;
        gather_add32_kernel<8><<<(int)((threads + 255) / 256), 256>>>(
            (const uint4*)p16, rowstart, blockoff, deg, edge_src, out, N);
    }
}